// round 10
// baseline (speedup 1.0000x reference)
#include <cuda_runtime.h>
#include <cuda_fp16.h>
#include <cstdint>
#include <cstddef>

#define B_ 2
#define S_ 2048
#define D_ 64
#define H_ 8

#define TM 128
#define TN 64
#define NTHREADS 160          // warps 0-3 consumers, warp 4 producer
#define NITER (S_ / TN)

// pitches in 32-bit words
#define PQW 36
#define PKW 36
#define PVW 36
#define PPW 72

// smem byte offsets
#define SMB   0                         // 6 mbarriers (8B each)
#define SQO   64
#define SK0O  (SQO  + TM*PQW*4)         // 18,496
#define SK1O  (SK0O + TN*PKW*4)
#define SV0O  (SK1O + TN*PKW*4)
#define SV1O  (SV0O + TN*PVW*4)
#define SPBO  (SV1O + TN*PVW*4)
#define SMEM_BYTES (SPBO + TM*PPW*4)    // 92,224 B -> 2 CTAs/SM

#define LOG2E 1.4426950408889634f

__device__ __forceinline__ uint32_t pack_h2(float lo, float hi) {
    uint32_t d;
    asm("cvt.rn.f16x2.f32 %0, %1, %2;" : "=r"(d) : "f"(hi), "f"(lo));
    return d;
}
__device__ __forceinline__ float ex2(float x) {
    float r; asm("ex2.approx.f32 %0, %1;" : "=f"(r) : "f"(x)); return r;
}
__device__ __forceinline__ void mma_f16(float c[4],
                                        uint32_t a0, uint32_t a1, uint32_t a2, uint32_t a3,
                                        uint32_t b0, uint32_t b1) {
    asm volatile(
        "mma.sync.aligned.m16n8k16.row.col.f32.f16.f16.f32 "
        "{%0,%1,%2,%3}, {%4,%5,%6,%7}, {%8,%9}, {%0,%1,%2,%3};\n"
        : "+f"(c[0]), "+f"(c[1]), "+f"(c[2]), "+f"(c[3])
        : "r"(a0), "r"(a1), "r"(a2), "r"(a3), "r"(b0), "r"(b1));
}
__device__ __forceinline__ void cp_async16(uint32_t dst_smem, const float* src) {
    asm volatile("cp.async.cg.shared.global [%0], [%1], 16;\n"
                 :: "r"(dst_smem), "l"(src));
}
__device__ __forceinline__ void mbar_init(uint32_t m, uint32_t cnt) {
    asm volatile("mbarrier.init.shared.b64 [%0], %1;" :: "r"(m), "r"(cnt) : "memory");
}
__device__ __forceinline__ void mbar_arrive(uint32_t m) {
    asm volatile("mbarrier.arrive.release.cta.shared::cta.b64 _, [%0];"
                 :: "r"(m) : "memory");
}
__device__ __forceinline__ void mbar_wait(uint32_t m, uint32_t parity) {
    asm volatile(
        "{\n\t.reg .pred P;\n\t"
        "WL%=:\n\t"
        "mbarrier.try_wait.parity.acquire.cta.shared::cta.b64 P, [%0], %1, 0x989680;\n\t"
        "@P bra.uni WD%=;\n\t"
        "bra.uni WL%=;\n\t"
        "WD%=:\n\t}"
        :: "r"(m), "r"(parity) : "memory");
}

__global__ void __launch_bounds__(NTHREADS, 2)
attn_bias_kernel(const float* __restrict__ x1,
                 const float* __restrict__ x2,
                 const float* __restrict__ x3,
                 const float* __restrict__ x4,
                 float* __restrict__ out) {
    const int mt = blockIdx.x;   // 0..15
    const int h  = blockIdx.y;   // 0..7
    const int b  = blockIdx.z;   // 0..1

    const int tid  = threadIdx.x;
    const int warp = tid >> 5;
    const int lane = tid & 31;
    const int r = lane >> 2;
    const int q = lane & 3;

    extern __shared__ uint32_t smem[];
    const uint32_t sb = (uint32_t)__cvta_generic_to_shared(smem);
    const uint32_t mb_kvf0 = sb + SMB + 0;
    const uint32_t mb_kvf1 = sb + SMB + 8;
    const uint32_t mb_kve0 = sb + SMB + 16;
    const uint32_t mb_kve1 = sb + SMB + 24;
    const uint32_t mb_bf   = sb + SMB + 32;
    const uint32_t mb_be   = sb + SMB + 40;

    uint32_t* sQ  = smem + SQO / 4;
    const float* sPBf = reinterpret_cast<const float*>(smem + SPBO / 4);

    if (tid == 0) {
        mbar_init(mb_kvf0, 32);  mbar_init(mb_kvf1, 32);
        mbar_init(mb_kve0, 128); mbar_init(mb_kve1, 128);
        mbar_init(mb_bf, 32);    mbar_init(mb_be, 128);
    }

    // ---- stage Q once (all 160 threads), fp16 pairs, pre-scaled ----
    const float qs = 0.125f * LOG2E;
    const float* qbase = x1 + ((size_t)b * S_ + (size_t)mt * TM) * D_;
    for (int i = tid; i < TM * 16; i += NTHREADS) {
        int row = i >> 4, c4 = i & 15;
        float4 v = *reinterpret_cast<const float4*>(qbase + row * D_ + 4 * c4);
        uint2 o;
        o.x = pack_h2(v.x * qs, v.y * qs);
        o.y = pack_h2(v.z * qs, v.w * qs);
        *reinterpret_cast<uint2*>(sQ + row * PQW + 2 * c4) = o;
    }
    __syncthreads();   // covers mbar init + Q

    if (warp == 4) {
        // ================= PRODUCER =================
        const int prow0 = lane >> 4;       // 0..1
        const int pc4   = lane & 15;       // 0..15
        const float* kp  = x2 + (size_t)b * S_ * D_ + (size_t)prow0 * D_ + pc4 * 4;
        const float* vpc = x4 + (size_t)b * S_ * D_;
        const float* bp  = x3 + (((size_t)b * H_ + h) * S_ + (size_t)mt * TM + prow0) * S_
                           + pc4 * 4;
        const uint32_t spb_b = sb + SPBO + (uint32_t)(prow0 * PPW + pc4 * 4) * 4;

        auto stage_kv = [&](int kbo, int vbo) {
            uint32_t* kw = smem + kbo / 4;
            uint32_t* vw = smem + vbo / 4;
            #pragma unroll 8
            for (int j = 0; j < 32; ++j) {
                float4 kv = *reinterpret_cast<const float4*>(kp + (size_t)(2 * j) * D_);
                uint2 o;
                o.x = pack_h2(kv.x, kv.y);
                o.y = pack_h2(kv.z, kv.w);
                *reinterpret_cast<uint2*>(kw + (prow0 + 2 * j) * PKW + 2 * pc4) = o;
            }
            kp += (size_t)TN * D_;
            #pragma unroll
            for (int sub = 0; sub < 4; ++sub) {
                int vt = lane + 32 * sub;
                int tp = vt >> 2, dq = vt & 3;
                const float* vp = vpc + (size_t)(2 * tp) * D_ + 16 * dq;
                uint32_t vx = (uint32_t)(tp ^ (dq << 3));
                #pragma unroll
                for (int jj = 0; jj < 4; ++jj) {
                    float4 va = *reinterpret_cast<const float4*>(vp + 4 * jj);
                    float4 vb = *reinterpret_cast<const float4*>(vp + D_ + 4 * jj);
                    int d0 = 16 * dq + 4 * jj;
                    vw[(d0 + 0) * PVW + vx] = pack_h2(va.x, vb.x);
                    vw[(d0 + 1) * PVW + vx] = pack_h2(va.y, vb.y);
                    vw[(d0 + 2) * PVW + vx] = pack_h2(va.z, vb.z);
                    vw[(d0 + 3) * PVW + vx] = pack_h2(va.w, vb.w);
                }
            }
            vpc += (size_t)TN * D_;
        };

        // prologue: bias(0) issue, KV(0), KV(1), bias(0) complete
        #pragma unroll 8
        for (int j = 0; j < 64; ++j)
            cp_async16(spb_b + (uint32_t)(2 * j * PPW) * 4, bp + (size_t)(2 * j) * S_);
        asm volatile("cp.async.commit_group;\n" ::: "memory");
        bp += TN;

        stage_kv(SK0O, SV0O);
        mbar_arrive(mb_kvf0);
        stage_kv(SK1O, SV1O);
        mbar_arrive(mb_kvf1);

        asm volatile("cp.async.wait_group 0;\n" ::: "memory");
        mbar_arrive(mb_bf);

        for (int it = 0; it < NITER; ++it) {
            if (it + 1 < NITER) {
                mbar_wait(mb_be, it & 1);          // consumers done reading bias(it)
                #pragma unroll 8
                for (int j = 0; j < 64; ++j)
                    cp_async16(spb_b + (uint32_t)(2 * j * PPW) * 4,
                               bp + (size_t)(2 * j) * S_);
                asm volatile("cp.async.commit_group;\n" ::: "memory");
                asm volatile("cp.async.wait_group 0;\n" ::: "memory");
                mbar_arrive(mb_bf);
                bp += TN;
            }
            if (it + 2 < NITER) {
                uint32_t mbe = (it & 1) ? mb_kve1 : mb_kve0;
                uint32_t mbf = (it & 1) ? mb_kvf1 : mb_kvf0;
                mbar_wait(mbe, (it >> 1) & 1);     // buf freed after PV(it)
                if (it & 1) stage_kv(SK1O, SV1O);
                else        stage_kv(SK0O, SV0O);
                mbar_arrive(mbf);
            }
        }
        return;
    }

    // ================= CONSUMERS (warps 0-3) =================
    float accO[2][8][4];
    #pragma unroll
    for (int mf = 0; mf < 2; ++mf)
        #pragma unroll
        for (int n = 0; n < 8; ++n)
            #pragma unroll
            for (int j = 0; j < 4; ++j) accO[mf][n][j] = 0.0f;
    float lsum[2][2] = {{0.0f, 0.0f}, {0.0f, 0.0f}};

    const int R0 = warp * 32;

    for (int it = 0; it < NITER; ++it) {
        const uint32_t mkvf = (it & 1) ? mb_kvf1 : mb_kvf0;
        const uint32_t mkve = (it & 1) ? mb_kve1 : mb_kve0;
        const uint32_t* sKb  = smem + ((it & 1) ? SK1O : SK0O) / 4;
        const uint32_t* sVTb = smem + ((it & 1) ? SV1O : SV0O) / 4;

        mbar_wait(mkvf, (it >> 1) & 1);

        // ---- QK: S = Q @ K^T, fp16 m16n8k16, 4 k-steps over d ----
        float c[2][8][4];
        #pragma unroll
        for (int mf = 0; mf < 2; ++mf)
            #pragma unroll
            for (int n = 0; n < 8; ++n)
                #pragma unroll
                for (int j = 0; j < 4; ++j) c[mf][n][j] = 0.0f;

        #pragma unroll
        for (int k = 0; k < 4; ++k) {
            uint32_t a[2][4];
            #pragma unroll
            for (int mf = 0; mf < 2; ++mf) {
                const uint32_t* qrow0 = sQ + (R0 + 16 * mf + r) * PQW + 8 * k + q;
                const uint32_t* qrow1 = sQ + (R0 + 16 * mf + r + 8) * PQW + 8 * k + q;
                a[mf][0] = qrow0[0];
                a[mf][1] = qrow1[0];
                a[mf][2] = qrow0[4];
                a[mf][3] = qrow1[4];
            }
            #pragma unroll
            for (int n = 0; n < 8; ++n) {
                const uint32_t* krow = sKb + (8 * n + r) * PKW + 8 * k + q;
                uint32_t b0 = krow[0];
                uint32_t b1 = krow[4];
                mma_f16(c[0][n], a[0][0], a[0][1], a[0][2], a[0][3], b0, b1);
                mma_f16(c[1][n], a[1][0], a[1][1], a[1][2], a[1][3], b0, b1);
            }
        }

        // ---- bias ready? ----
        mbar_wait(mb_bf, it & 1);

        // ---- softmax: exp2, P packed to fp16 registers ----
        uint32_t pk[2][8][2];
        #pragma unroll
        for (int mf = 0; mf < 2; ++mf) {
            const int R = R0 + 16 * mf;
            #pragma unroll
            for (int n = 0; n < 8; ++n) {
                float2 bb0 = *reinterpret_cast<const float2*>(sPBf + (R + r) * PPW + 8 * n + 2 * q);
                float2 bb1 = *reinterpret_cast<const float2*>(sPBf + (R + r + 8) * PPW + 8 * n + 2 * q);
                float p0 = ex2(fmaf(bb0.x, LOG2E, c[mf][n][0]));
                float p1 = ex2(fmaf(bb0.y, LOG2E, c[mf][n][1]));
                float p2 = ex2(fmaf(bb1.x, LOG2E, c[mf][n][2]));
                float p3 = ex2(fmaf(bb1.y, LOG2E, c[mf][n][3]));
                lsum[mf][0] += p0 + p1;
                lsum[mf][1] += p2 + p3;
                pk[mf][n][0] = pack_h2(p0, p1);
                pk[mf][n][1] = pack_h2(p2, p3);
            }
        }
        mbar_arrive(mb_be);   // done reading bias(it)

        // ---- PV: O += P @ V ; A from registers, B from sVT ----
        #pragma unroll
        for (int n = 0; n < 8; ++n) {
            const int d = 8 * n + r;
            const uint32_t f = (uint32_t)(((d >> 4) & 3) << 3);
            const uint32_t* vrow = sVTb + d * PVW;
            #pragma unroll
            for (int k = 0; k < 4; ++k) {
                uint32_t b0 = vrow[(uint32_t)(8 * k + q) ^ f];
                uint32_t b1 = vrow[(uint32_t)(8 * k + q + 4) ^ f];
                mma_f16(accO[0][n], pk[0][2*k][0], pk[0][2*k][1],
                                    pk[0][2*k+1][0], pk[0][2*k+1][1], b0, b1);
                mma_f16(accO[1][n], pk[1][2*k][0], pk[1][2*k][1],
                                    pk[1][2*k+1][0], pk[1][2*k+1][1], b0, b1);
            }
        }
        mbar_arrive(mkve);    // K/V buffer free
    }

    // ---- finalize: quad-reduce row sums, divide, store ----
    #pragma unroll
    for (int mf = 0; mf < 2; ++mf)
        #pragma unroll
        for (int j = 0; j < 2; ++j) {
            lsum[mf][j] += __shfl_xor_sync(0xffffffffu, lsum[mf][j], 1);
            lsum[mf][j] += __shfl_xor_sync(0xffffffffu, lsum[mf][j], 2);
        }

    float inv[2][2];
    inv[0][0] = 1.0f / lsum[0][0]; inv[0][1] = 1.0f / lsum[0][1];
    inv[1][0] = 1.0f / lsum[1][0]; inv[1][1] = 1.0f / lsum[1][1];

    float* obase = out + (((size_t)b * H_ + h) * S_ + (size_t)mt * TM) * D_;
    #pragma unroll
    for (int mf = 0; mf < 2; ++mf) {
        const int R = R0 + 16 * mf;
        #pragma unroll
        for (int n = 0; n < 8; ++n) {
            float2 v0 = make_float2(accO[mf][n][0] * inv[mf][0], accO[mf][n][1] * inv[mf][0]);
            float2 v1 = make_float2(accO[mf][n][2] * inv[mf][1], accO[mf][n][3] * inv[mf][1]);
            *reinterpret_cast<float2*>(obase + (size_t)(R + r) * D_ + 8 * n + 2 * q) = v0;
            *reinterpret_cast<float2*>(obase + (size_t)(R + r + 8) * D_ + 8 * n + 2 * q) = v1;
        }
    }
}

extern "C" void kernel_launch(void* const* d_in, const int* in_sizes, int n_in,
                              void* d_out, int out_size) {
    (void)in_sizes; (void)n_in; (void)out_size;
    const float* x1 = (const float*)d_in[0];
    const float* x2 = (const float*)d_in[1];
    const float* x3 = (const float*)d_in[2];
    const float* x4 = (const float*)d_in[3];
    float* out = (float*)d_out;

    cudaFuncSetAttribute(attn_bias_kernel,
                         cudaFuncAttributeMaxDynamicSharedMemorySize, SMEM_BYTES);

    dim3 grid(S_ / TM, H_, B_);   // 16 x 8 x 2 = 256 CTAs
    attn_bias_kernel<<<grid, NTHREADS, SMEM_BYTES>>>(x1, x2, x3, x4, out);
}

// round 11
// speedup vs baseline: 1.1124x; 1.1124x over previous
#include <cuda_runtime.h>
#include <cuda_fp16.h>
#include <cstdint>
#include <cstddef>

#define B_ 2
#define S_ 2048
#define D_ 64
#define H_ 8

#define TM 128
#define TN 64
#define NTHREADS 128
#define NITER (S_ / TN)

// pitches in 32-bit words
#define PQW 36   // Q fp16 pairs
#define PKW 36   // K fp16 pairs
#define PVW 36   // V^T fp16 pairs
#define PRW 68   // raw fp32 staging (272B rows: 16B-aligned, conflict-tolerable)

// smem word offsets
#define OQ   0
#define OKF  (OQ   + TM*PQW)
#define OVT  (OKF  + TN*PKW)
#define ORK0 (OVT  + TN*PVW)
#define ORK1 (ORK0 + TN*PRW)
#define ORV0 (ORK1 + TN*PRW)
#define ORV1 (ORV0 + TN*PRW)
#define SMEM_WORDS (ORV1 + TN*PRW)
#define SMEM_BYTES (SMEM_WORDS * 4)     // 106,496 B -> 2 CTAs/SM

#define LOG2E 1.4426950408889634f

__device__ __forceinline__ uint32_t pack_h2(float lo, float hi) {
    uint32_t d;
    asm("cvt.rn.f16x2.f32 %0, %1, %2;" : "=r"(d) : "f"(hi), "f"(lo));
    return d;
}
__device__ __forceinline__ float ex2(float x) {
    float r; asm("ex2.approx.f32 %0, %1;" : "=f"(r) : "f"(x)); return r;
}
__device__ __forceinline__ void mma_f16(float c[4],
                                        uint32_t a0, uint32_t a1, uint32_t a2, uint32_t a3,
                                        uint32_t b0, uint32_t b1) {
    asm volatile(
        "mma.sync.aligned.m16n8k16.row.col.f32.f16.f16.f32 "
        "{%0,%1,%2,%3}, {%4,%5,%6,%7}, {%8,%9}, {%0,%1,%2,%3};\n"
        : "+f"(c[0]), "+f"(c[1]), "+f"(c[2]), "+f"(c[3])
        : "r"(a0), "r"(a1), "r"(a2), "r"(a3), "r"(b0), "r"(b1));
}
__device__ __forceinline__ void cp_async16(uint32_t dst_smem, const float* src) {
    asm volatile("cp.async.cg.shared.global [%0], [%1], 16;\n"
                 :: "r"(dst_smem), "l"(src));
}

__global__ void __launch_bounds__(NTHREADS, 2)
attn_bias_kernel(const float* __restrict__ x1,
                 const float* __restrict__ x2,
                 const float* __restrict__ x3,
                 const float* __restrict__ x4,
                 float* __restrict__ out) {
    const int mt = blockIdx.x;   // 0..15
    const int h  = blockIdx.y;   // 0..7
    const int b  = blockIdx.z;   // 0..1

    const int tid  = threadIdx.x;
    const int warp = tid >> 5;
    const int lane = tid & 31;
    const int r = lane >> 2;
    const int q = lane & 3;

    extern __shared__ uint32_t smem[];
    const uint32_t sb = (uint32_t)__cvta_generic_to_shared(smem);
    uint32_t* sQ  = smem + OQ;
    uint32_t* sKf = smem + OKF;
    uint32_t* sVT = smem + OVT;

    // ---- stage Q once: fp16 pairs, pre-scaled by 0.125*log2e ----
    const float qs = 0.125f * LOG2E;
    const int srowK = tid >> 4;          // 0..7
    const int sc4   = tid & 15;          // 0..15
    const float* qbase = x1 + ((size_t)b * S_ + (size_t)mt * TM) * D_;
    #pragma unroll
    for (int j = 0; j < 16; ++j) {
        int row = srowK + 8 * j;
        float4 v = *reinterpret_cast<const float4*>(qbase + row * D_ + 4 * sc4);
        uint2 o;
        o.x = pack_h2(v.x * qs, v.y * qs);
        o.y = pack_h2(v.z * qs, v.w * qs);
        *reinterpret_cast<uint2*>(sQ + row * PQW + 2 * sc4) = o;
    }

    // ---- cp.async staging pointers (thread covers rows srowK+8j, chunk sc4) ----
    const float* kcp = x2 + (size_t)b * S_ * D_ + (size_t)srowK * D_ + sc4 * 4;
    const float* vcp = x4 + (size_t)b * S_ * D_ + (size_t)srowK * D_ + sc4 * 4;
    const uint32_t rkd = sb + 4u * (uint32_t)(srowK * PRW + 4 * sc4);   // + ORKx*4
    const uint32_t rvd = rkd;                                           // same shape

    // ---- prologue: issue raw K/V tile 0 ----
    #pragma unroll
    for (int j = 0; j < 8; ++j) {
        cp_async16(rkd + 4u * (uint32_t)(ORK0 + 8 * j * PRW), kcp + (size_t)(8 * j) * D_);
        cp_async16(rvd + 4u * (uint32_t)(ORV0 + 8 * j * PRW), vcp + (size_t)(8 * j) * D_);
    }
    asm volatile("cp.async.commit_group;\n" ::: "memory");
    kcp += (size_t)TN * D_;
    vcp += (size_t)TN * D_;

    float accO[2][8][4];
    #pragma unroll
    for (int mf = 0; mf < 2; ++mf)
        #pragma unroll
        for (int n = 0; n < 8; ++n)
            #pragma unroll
            for (int j = 0; j < 4; ++j) accO[mf][n][j] = 0.0f;
    float lsum[2][2] = {{0.0f, 0.0f}, {0.0f, 0.0f}};

    const int R0 = warp * 32;

    // ---- bias row pointers (direct, coalesced float2 LDG) ----
    const float* xb = x3 + (((size_t)b * H_ + h) * S_ + (size_t)mt * TM) * S_ + 2 * q;
    const float* bpA = xb + (size_t)(R0 + r) * S_;
    const float* bpB = xb + (size_t)(R0 + r + 8) * S_;
    const float* bpC = xb + (size_t)(R0 + 16 + r) * S_;
    const float* bpD = xb + (size_t)(R0 + 24 + r) * S_;

    // V transpose conversion geometry (R9 pattern, source = raw smem)
    const int tp = tid >> 2;             // 0..31
    const int dq = tid & 3;              // 0..3
    const uint32_t vxor = (uint32_t)(tp ^ (dq << 3));

    for (int it = 0; it < NITER; ++it) {
        // ---- 1. bias LDGs -> registers (consumed after QK) ----
        float2 bA[8], bB[8], bC[8], bD[8];
        #pragma unroll
        for (int n = 0; n < 8; ++n) {
            bA[n] = *reinterpret_cast<const float2*>(bpA + 8 * n);
            bB[n] = *reinterpret_cast<const float2*>(bpB + 8 * n);
            bC[n] = *reinterpret_cast<const float2*>(bpC + 8 * n);
            bD[n] = *reinterpret_cast<const float2*>(bpD + 8 * n);
        }
        bpA += TN; bpB += TN; bpC += TN; bpD += TN;

        // ---- 2-3. raw K/V(it) complete + visible; fp16 tiles free ----
        asm volatile("cp.async.wait_group 0;\n" ::: "memory");
        __syncthreads();

        // ---- 4. issue raw K/V(it+1) into the other buffer ----
        if (it + 1 < NITER) {
            const uint32_t ok = ((it + 1) & 1) ? (uint32_t)ORK1 : (uint32_t)ORK0;
            const uint32_t ov = ((it + 1) & 1) ? (uint32_t)ORV1 : (uint32_t)ORV0;
            #pragma unroll
            for (int j = 0; j < 8; ++j) {
                cp_async16(rkd + 4u * (ok + 8 * j * PRW), kcp + (size_t)(8 * j) * D_);
                cp_async16(rvd + 4u * (ov + 8 * j * PRW), vcp + (size_t)(8 * j) * D_);
            }
            asm volatile("cp.async.commit_group;\n" ::: "memory");
            kcp += (size_t)TN * D_;
            vcp += (size_t)TN * D_;
        }

        // ---- 5. convert raw(it) -> fp16 tiles ----
        const float* rawK = reinterpret_cast<const float*>(
            smem + ((it & 1) ? ORK1 : ORK0));
        const float* rawV = reinterpret_cast<const float*>(
            smem + ((it & 1) ? ORV1 : ORV0));
        #pragma unroll
        for (int j = 0; j < 8; ++j) {
            int row = srowK + 8 * j;
            float4 v = *reinterpret_cast<const float4*>(rawK + row * PRW + 4 * sc4);
            uint2 o;
            o.x = pack_h2(v.x, v.y);
            o.y = pack_h2(v.z, v.w);
            *reinterpret_cast<uint2*>(sKf + row * PKW + 2 * sc4) = o;
        }
        #pragma unroll
        for (int jj = 0; jj < 4; ++jj) {
            float4 va = *reinterpret_cast<const float4*>(rawV + (2 * tp) * PRW + 16 * dq + 4 * jj);
            float4 vb = *reinterpret_cast<const float4*>(rawV + (2 * tp + 1) * PRW + 16 * dq + 4 * jj);
            int d0 = 16 * dq + 4 * jj;
            sVT[(d0 + 0) * PVW + vxor] = pack_h2(va.x, vb.x);
            sVT[(d0 + 1) * PVW + vxor] = pack_h2(va.y, vb.y);
            sVT[(d0 + 2) * PVW + vxor] = pack_h2(va.z, vb.z);
            sVT[(d0 + 3) * PVW + vxor] = pack_h2(va.w, vb.w);
        }

        // ---- 6. fp16 tiles ready ----
        __syncthreads();

        // ---- 7. QK: S = Q @ K^T, fp16 m16n8k16 ----
        float c[2][8][4];
        #pragma unroll
        for (int mf = 0; mf < 2; ++mf)
            #pragma unroll
            for (int n = 0; n < 8; ++n)
                #pragma unroll
                for (int j = 0; j < 4; ++j) c[mf][n][j] = 0.0f;

        #pragma unroll
        for (int k = 0; k < 4; ++k) {
            uint32_t a[2][4];
            #pragma unroll
            for (int mf = 0; mf < 2; ++mf) {
                const uint32_t* qrow0 = sQ + (R0 + 16 * mf + r) * PQW + 8 * k + q;
                const uint32_t* qrow1 = sQ + (R0 + 16 * mf + r + 8) * PQW + 8 * k + q;
                a[mf][0] = qrow0[0];
                a[mf][1] = qrow1[0];
                a[mf][2] = qrow0[4];
                a[mf][3] = qrow1[4];
            }
            #pragma unroll
            for (int n = 0; n < 8; ++n) {
                const uint32_t* krow = sKf + (8 * n + r) * PKW + 8 * k + q;
                uint32_t b0 = krow[0];
                uint32_t b1 = krow[4];
                mma_f16(c[0][n], a[0][0], a[0][1], a[0][2], a[0][3], b0, b1);
                mma_f16(c[1][n], a[1][0], a[1][1], a[1][2], a[1][3], b0, b1);
            }
        }

        // ---- 8. softmax with register bias; P packed to fp16 registers ----
        uint32_t pk[2][8][2];
        #pragma unroll
        for (int n = 0; n < 8; ++n) {
            float p0 = ex2(fmaf(bA[n].x, LOG2E, c[0][n][0]));
            float p1 = ex2(fmaf(bA[n].y, LOG2E, c[0][n][1]));
            float p2 = ex2(fmaf(bB[n].x, LOG2E, c[0][n][2]));
            float p3 = ex2(fmaf(bB[n].y, LOG2E, c[0][n][3]));
            lsum[0][0] += p0 + p1;
            lsum[0][1] += p2 + p3;
            pk[0][n][0] = pack_h2(p0, p1);
            pk[0][n][1] = pack_h2(p2, p3);
        }
        #pragma unroll
        for (int n = 0; n < 8; ++n) {
            float p0 = ex2(fmaf(bC[n].x, LOG2E, c[1][n][0]));
            float p1 = ex2(fmaf(bC[n].y, LOG2E, c[1][n][1]));
            float p2 = ex2(fmaf(bD[n].x, LOG2E, c[1][n][2]));
            float p3 = ex2(fmaf(bD[n].y, LOG2E, c[1][n][3]));
            lsum[1][0] += p0 + p1;
            lsum[1][1] += p2 + p3;
            pk[1][n][0] = pack_h2(p0, p1);
            pk[1][n][1] = pack_h2(p2, p3);
        }

        // ---- 9. PV: O += P @ V ; A from registers, B from sVT ----
        #pragma unroll
        for (int n = 0; n < 8; ++n) {
            const int d = 8 * n + r;
            const uint32_t f = (uint32_t)(((d >> 4) & 3) << 3);
            const uint32_t* vrow = sVT + d * PVW;
            #pragma unroll
            for (int k = 0; k < 4; ++k) {
                uint32_t b0 = vrow[(uint32_t)(8 * k + q) ^ f];
                uint32_t b1 = vrow[(uint32_t)(8 * k + q + 4) ^ f];
                mma_f16(accO[0][n], pk[0][2*k][0], pk[0][2*k][1],
                                    pk[0][2*k+1][0], pk[0][2*k+1][1], b0, b1);
                mma_f16(accO[1][n], pk[1][2*k][0], pk[1][2*k][1],
                                    pk[1][2*k+1][0], pk[1][2*k+1][1], b0, b1);
            }
        }
    }

    // ---- finalize: quad-reduce row sums, divide, store ----
    #pragma unroll
    for (int mf = 0; mf < 2; ++mf)
        #pragma unroll
        for (int j = 0; j < 2; ++j) {
            lsum[mf][j] += __shfl_xor_sync(0xffffffffu, lsum[mf][j], 1);
            lsum[mf][j] += __shfl_xor_sync(0xffffffffu, lsum[mf][j], 2);
        }

    float inv[2][2];
    inv[0][0] = 1.0f / lsum[0][0]; inv[0][1] = 1.0f / lsum[0][1];
    inv[1][0] = 1.0f / lsum[1][0]; inv[1][1] = 1.0f / lsum[1][1];

    float* obase = out + (((size_t)b * H_ + h) * S_ + (size_t)mt * TM) * D_;
    #pragma unroll
    for (int mf = 0; mf < 2; ++mf) {
        const int R = R0 + 16 * mf;
        #pragma unroll
        for (int n = 0; n < 8; ++n) {
            float2 v0 = make_float2(accO[mf][n][0] * inv[mf][0], accO[mf][n][1] * inv[mf][0]);
            float2 v1 = make_float2(accO[mf][n][2] * inv[mf][1], accO[mf][n][3] * inv[mf][1]);
            *reinterpret_cast<float2*>(obase + (size_t)(R + r) * D_ + 8 * n + 2 * q) = v0;
            *reinterpret_cast<float2*>(obase + (size_t)(R + r + 8) * D_ + 8 * n + 2 * q) = v1;
        }
    }
}

extern "C" void kernel_launch(void* const* d_in, const int* in_sizes, int n_in,
                              void* d_out, int out_size) {
    (void)in_sizes; (void)n_in; (void)out_size;
    const float* x1 = (const float*)d_in[0];
    const float* x2 = (const float*)d_in[1];
    const float* x3 = (const float*)d_in[2];
    const float* x4 = (const float*)d_in[3];
    float* out = (float*)d_out;

    cudaFuncSetAttribute(attn_bias_kernel,
                         cudaFuncAttributeMaxDynamicSharedMemorySize, SMEM_BYTES);

    dim3 grid(S_ / TM, H_, B_);   // 16 x 8 x 2 = 256 CTAs
    attn_bias_kernel<<<grid, NTHREADS, SMEM_BYTES>>>(x1, x2, x3, x4, out);
}

// round 12
// speedup vs baseline: 1.2577x; 1.1306x over previous
#include <cuda_runtime.h>
#include <cuda_fp16.h>
#include <cstdint>
#include <cstddef>

#define B_ 2
#define S_ 2048
#define D_ 64
#define H_ 8

#define TM 128
#define TN 64
#define NTHREADS 128
#define NSPLIT 2
#define ITERS (S_ / TN / NSPLIT)    // 16

// pitches in 32-bit words
#define PQW 36   // Q fp16 pairs
#define PKW 36   // K fp16 pairs
#define PVW 36   // V^T fp16 pairs
#define PPW 72   // bias fp32

#define SMEM_WORDS (TM*PQW + TN*PKW + TN*PVW + TM*PPW)
#define SMEM_BYTES (SMEM_WORDS * 4)   // 73,728 B -> 3 CTAs/SM (221KB)

#define LOG2E 1.4426950408889634f

// scratch for split-K partials (device globals: allocation-free)
__device__ float g_part[NSPLIT][B_ * H_ * S_ * D_];
__device__ float g_lsum[NSPLIT][B_ * H_ * S_];

__device__ __forceinline__ uint32_t pack_h2(float lo, float hi) {
    uint32_t d;
    asm("cvt.rn.f16x2.f32 %0, %1, %2;" : "=r"(d) : "f"(hi), "f"(lo));
    return d;
}
__device__ __forceinline__ float ex2(float x) {
    float r; asm("ex2.approx.f32 %0, %1;" : "=f"(r) : "f"(x)); return r;
}
__device__ __forceinline__ void mma_f16(float c[4],
                                        uint32_t a0, uint32_t a1, uint32_t a2, uint32_t a3,
                                        uint32_t b0, uint32_t b1) {
    asm volatile(
        "mma.sync.aligned.m16n8k16.row.col.f32.f16.f16.f32 "
        "{%0,%1,%2,%3}, {%4,%5,%6,%7}, {%8,%9}, {%0,%1,%2,%3};\n"
        : "+f"(c[0]), "+f"(c[1]), "+f"(c[2]), "+f"(c[3])
        : "r"(a0), "r"(a1), "r"(a2), "r"(a3), "r"(b0), "r"(b1));
}
__device__ __forceinline__ void cp_async16(uint32_t dst_smem, const float* src) {
    asm volatile("cp.async.cg.shared.global [%0], [%1], 16;\n"
                 :: "r"(dst_smem), "l"(src));
}

__global__ void __launch_bounds__(NTHREADS, 3)
attn_bias_kernel(const float* __restrict__ x1,
                 const float* __restrict__ x2,
                 const float* __restrict__ x3,
                 const float* __restrict__ x4) {
    const int mt = blockIdx.x;          // 0..15
    const int h  = blockIdx.y;          // 0..7
    const int b  = blockIdx.z >> 1;     // 0..1
    const int sp = blockIdx.z & 1;      // 0..1 (t-split)
    const int tbase = sp * (S_ / NSPLIT);

    const int tid  = threadIdx.x;
    const int warp = tid >> 5;
    const int lane = tid & 31;
    const int r = lane >> 2;
    const int q = lane & 3;

    extern __shared__ uint32_t smem[];
    uint32_t* sQ  = smem;                 // [TM][PQW]  fp16 pairs, pre-scaled
    uint32_t* sK  = sQ + TM * PQW;        // [TN][PKW]  fp16 pairs (d-packed)
    uint32_t* sVT = sK + TN * PKW;        // [64][PVW]  fp16 pairs (t-packed, xor)
    uint32_t* sPB = sVT + TN * PVW;       // [TM][PPW]  bias fp32
    const float* sPBf = reinterpret_cast<const float*>(sPB);

    // ---- stage Q once: fp16, pre-scaled by 0.125*log2e ----
    const float qs = 0.125f * LOG2E;
    const int srowK = tid >> 4;          // 0..7
    const int sc4   = tid & 15;          // 0..15
    const float* qbase = x1 + ((size_t)b * S_ + (size_t)mt * TM) * D_;
    #pragma unroll
    for (int j = 0; j < 16; ++j) {
        int row = srowK + 8 * j;
        float4 v = *reinterpret_cast<const float4*>(qbase + row * D_ + 4 * sc4);
        uint2 o;
        o.x = pack_h2(v.x * qs, v.y * qs);
        o.y = pack_h2(v.z * qs, v.w * qs);
        *reinterpret_cast<uint2*>(sQ + row * PQW + 2 * sc4) = o;
    }

    float accO[2][8][4];
    #pragma unroll
    for (int mf = 0; mf < 2; ++mf)
        #pragma unroll
        for (int n = 0; n < 8; ++n)
            #pragma unroll
            for (int j = 0; j < 4; ++j) accO[mf][n][j] = 0.0f;
    float lsum[2][2] = {{0.0f, 0.0f}, {0.0f, 0.0f}};

    const int R0 = warp * 32;

    // ---- staging pointers ----
    const float* kptr = x2 + ((size_t)b * S_ + tbase) * D_ + (size_t)srowK * D_ + sc4 * 4;
    const int tp = tid >> 2;             // 0..31
    const int dq = tid & 3;              // 0..3
    const float* vptr = x4 + ((size_t)b * S_ + tbase) * D_ + (size_t)(2 * tp) * D_ + 16 * dq;
    const uint32_t vxor = (uint32_t)(tp ^ (dq << 3));
    const int brow0 = warp * 32 + (lane >> 4);
    const int bc4   = lane & 15;
    const float* bptr = x3 + (((size_t)b * H_ + h) * S_ + (size_t)mt * TM + brow0) * S_
                        + tbase + bc4 * 4;
    const uint32_t sPB_b = (uint32_t)__cvta_generic_to_shared(sPB)
                         + (uint32_t)(brow0 * PPW + bc4 * 4) * 4;

    for (int it = 0; it < ITERS; ++it) {
        __syncthreads();   // prev iteration's sK/sVT/sPB readers done

        // ---- bias tile cp.async first (overlaps staging + QK) ----
        #pragma unroll
        for (int j = 0; j < 16; ++j)
            cp_async16(sPB_b + (uint32_t)(2 * j * PPW) * 4, bptr + (size_t)(2 * j) * S_);
        asm volatile("cp.async.commit_group;\n" ::: "memory");
        bptr += TN;

        // ---- stage K: fp16 pairs along d, row-major [t][d] ----
        #pragma unroll
        for (int j = 0; j < 8; ++j) {
            int row = srowK + 8 * j;
            float4 v = *reinterpret_cast<const float4*>(kptr + (size_t)(8 * j) * D_);
            uint2 o;
            o.x = pack_h2(v.x, v.y);
            o.y = pack_h2(v.z, v.w);
            *reinterpret_cast<uint2*>(sK + row * PKW + 2 * sc4) = o;
        }
        kptr += (size_t)TN * D_;

        // ---- stage V transposed: VT[d][t], fp16 pairs along t, xor-swizzled ----
        #pragma unroll
        for (int jj = 0; jj < 4; ++jj) {
            float4 va = *reinterpret_cast<const float4*>(vptr + 4 * jj);
            float4 vb = *reinterpret_cast<const float4*>(vptr + D_ + 4 * jj);
            int d0 = 16 * dq + 4 * jj;
            sVT[(d0 + 0) * PVW + vxor] = pack_h2(va.x, vb.x);
            sVT[(d0 + 1) * PVW + vxor] = pack_h2(va.y, vb.y);
            sVT[(d0 + 2) * PVW + vxor] = pack_h2(va.z, vb.z);
            sVT[(d0 + 3) * PVW + vxor] = pack_h2(va.w, vb.w);
        }
        vptr += (size_t)TN * D_;
        __syncthreads();   // sK/sVT visible (bias still in flight)

        // ---- QK: S = Q @ K^T, fp16 m16n8k16, 4 k-steps over d ----
        float c[2][8][4];
        #pragma unroll
        for (int mf = 0; mf < 2; ++mf)
            #pragma unroll
            for (int n = 0; n < 8; ++n)
                #pragma unroll
                for (int j = 0; j < 4; ++j) c[mf][n][j] = 0.0f;

        #pragma unroll
        for (int k = 0; k < 4; ++k) {
            uint32_t a[2][4];
            #pragma unroll
            for (int mf = 0; mf < 2; ++mf) {
                const uint32_t* qrow0 = sQ + (R0 + 16 * mf + r) * PQW + 8 * k + q;
                const uint32_t* qrow1 = sQ + (R0 + 16 * mf + r + 8) * PQW + 8 * k + q;
                a[mf][0] = qrow0[0];
                a[mf][1] = qrow1[0];
                a[mf][2] = qrow0[4];
                a[mf][3] = qrow1[4];
            }
            #pragma unroll
            for (int n = 0; n < 8; ++n) {
                const uint32_t* krow = sK + (8 * n + r) * PKW + 8 * k + q;
                uint32_t b0 = krow[0];
                uint32_t b1 = krow[4];
                mma_f16(c[0][n], a[0][0], a[0][1], a[0][2], a[0][3], b0, b1);
                mma_f16(c[1][n], a[1][0], a[1][1], a[1][2], a[1][3], b0, b1);
            }
        }

        // ---- bias ready; warp-local wait ----
        asm volatile("cp.async.wait_group 0;\n" ::: "memory");
        __syncwarp();

        // ---- softmax: exp2, P packed to fp16 registers ----
        uint32_t pk[2][8][2];
        #pragma unroll
        for (int mf = 0; mf < 2; ++mf) {
            const int R = R0 + 16 * mf;
            #pragma unroll
            for (int n = 0; n < 8; ++n) {
                float2 bb0 = *reinterpret_cast<const float2*>(sPBf + (R + r) * PPW + 8 * n + 2 * q);
                float2 bb1 = *reinterpret_cast<const float2*>(sPBf + (R + r + 8) * PPW + 8 * n + 2 * q);
                float p0 = ex2(fmaf(bb0.x, LOG2E, c[mf][n][0]));
                float p1 = ex2(fmaf(bb0.y, LOG2E, c[mf][n][1]));
                float p2 = ex2(fmaf(bb1.x, LOG2E, c[mf][n][2]));
                float p3 = ex2(fmaf(bb1.y, LOG2E, c[mf][n][3]));
                lsum[mf][0] += p0 + p1;
                lsum[mf][1] += p2 + p3;
                pk[mf][n][0] = pack_h2(p0, p1);
                pk[mf][n][1] = pack_h2(p2, p3);
            }
        }

        // ---- PV: O += P @ V ; A from registers, B from sVT ----
        #pragma unroll
        for (int n = 0; n < 8; ++n) {
            const int d = 8 * n + r;
            const uint32_t f = (uint32_t)(((d >> 4) & 3) << 3);
            const uint32_t* vrow = sVT + d * PVW;
            #pragma unroll
            for (int k = 0; k < 4; ++k) {
                uint32_t b0 = vrow[(uint32_t)(8 * k + q) ^ f];
                uint32_t b1 = vrow[(uint32_t)(8 * k + q + 4) ^ f];
                mma_f16(accO[0][n], pk[0][2*k][0], pk[0][2*k][1],
                                    pk[0][2*k+1][0], pk[0][2*k+1][1], b0, b1);
                mma_f16(accO[1][n], pk[1][2*k][0], pk[1][2*k][1],
                                    pk[1][2*k+1][0], pk[1][2*k+1][1], b0, b1);
            }
        }
    }

    // ---- epilogue: quad-reduce row sums; write UNNORMALIZED partials ----
    #pragma unroll
    for (int mf = 0; mf < 2; ++mf)
        #pragma unroll
        for (int j = 0; j < 2; ++j) {
            lsum[mf][j] += __shfl_xor_sync(0xffffffffu, lsum[mf][j], 1);
            lsum[mf][j] += __shfl_xor_sync(0xffffffffu, lsum[mf][j], 2);
        }

    const size_t rowbase = ((size_t)b * H_ + h) * S_ + (size_t)mt * TM;
    float* pbase = g_part[sp] + rowbase * D_;
    #pragma unroll
    for (int mf = 0; mf < 2; ++mf) {
        const int R = R0 + 16 * mf;
        #pragma unroll
        for (int n = 0; n < 8; ++n) {
            float2 v0 = make_float2(accO[mf][n][0], accO[mf][n][1]);
            float2 v1 = make_float2(accO[mf][n][2], accO[mf][n][3]);
            *reinterpret_cast<float2*>(pbase + (size_t)(R + r) * D_ + 8 * n + 2 * q) = v0;
            *reinterpret_cast<float2*>(pbase + (size_t)(R + r + 8) * D_ + 8 * n + 2 * q) = v1;
        }
    }
    if (q == 0) {
        #pragma unroll
        for (int mf = 0; mf < 2; ++mf) {
            const int R = R0 + 16 * mf;
            g_lsum[sp][rowbase + R + r]     = lsum[mf][0];
            g_lsum[sp][rowbase + R + r + 8] = lsum[mf][1];
        }
    }
}

__global__ void combine_kernel(float* __restrict__ out) {
    const int total = B_ * H_ * S_ * (D_ / 4);    // float4 count
    int i = blockIdx.x * blockDim.x + threadIdx.x;
    if (i >= total) return;
    int row = i >> 4;                              // D_/4 = 16 float4 per row
    const float4* p0 = reinterpret_cast<const float4*>(g_part[0]);
    const float4* p1 = reinterpret_cast<const float4*>(g_part[1]);
    float4 a = p0[i];
    float4 c = p1[i];
    float inv = 1.0f / (g_lsum[0][row] + g_lsum[1][row]);
    float4 o;
    o.x = (a.x + c.x) * inv;
    o.y = (a.y + c.y) * inv;
    o.z = (a.z + c.z) * inv;
    o.w = (a.w + c.w) * inv;
    reinterpret_cast<float4*>(out)[i] = o;
}

extern "C" void kernel_launch(void* const* d_in, const int* in_sizes, int n_in,
                              void* d_out, int out_size) {
    (void)in_sizes; (void)n_in; (void)out_size;
    const float* x1 = (const float*)d_in[0];
    const float* x2 = (const float*)d_in[1];
    const float* x3 = (const float*)d_in[2];
    const float* x4 = (const float*)d_in[3];
    float* out = (float*)d_out;

    cudaFuncSetAttribute(attn_bias_kernel,
                         cudaFuncAttributeMaxDynamicSharedMemorySize, SMEM_BYTES);

    dim3 grid(S_ / TM, H_, B_ * NSPLIT);   // 16 x 8 x 4 = 512 CTAs
    attn_bias_kernel<<<grid, NTHREADS, SMEM_BYTES>>>(x1, x2, x3, x4);

    const int total = B_ * H_ * S_ * (D_ / 4);
    combine_kernel<<<(total + 255) / 256, 256>>>(out);
}

// round 13
// speedup vs baseline: 1.5644x; 1.2439x over previous
#include <cuda_runtime.h>
#include <cuda_fp16.h>
#include <cstdint>
#include <cstddef>

#define B_ 2
#define S_ 2048
#define D_ 64
#define H_ 8

#define TM 128
#define TN 64
#define NTHREADS 128
#define NITER (S_ / TN)

// pitches in 32-bit words
#define PQW 36   // Q fp16 pairs
#define PKW 36   // K fp16 pairs
#define PVW 36   // V^T fp16 pairs
#define PPW 72   // bias fp32
#define PRW 68   // raw fp32 K/V staging

// smem word offsets
#define OQ   0
#define OKF  (OQ  + TM*PQW)      // 4608
#define OVT  (OKF + TN*PKW)      // 6912
#define OPB  (OVT + TN*PVW)      // 9216
#define ORK  (OPB + TM*PPW)      // 18432
#define ORV  (ORK + TN*PRW)      // 22784
#define SMEM_WORDS (ORV + TN*PRW)
#define SMEM_BYTES (SMEM_WORDS * 4)   // 108,544 B -> 2 CTAs/SM

#define LOG2E 1.4426950408889634f

__device__ __forceinline__ uint32_t pack_h2(float lo, float hi) {
    uint32_t d;
    asm("cvt.rn.f16x2.f32 %0, %1, %2;" : "=r"(d) : "f"(hi), "f"(lo));
    return d;
}
__device__ __forceinline__ float ex2(float x) {
    float r; asm("ex2.approx.f32 %0, %1;" : "=f"(r) : "f"(x)); return r;
}
__device__ __forceinline__ void mma_f16(float c[4],
                                        uint32_t a0, uint32_t a1, uint32_t a2, uint32_t a3,
                                        uint32_t b0, uint32_t b1) {
    asm volatile(
        "mma.sync.aligned.m16n8k16.row.col.f32.f16.f16.f32 "
        "{%0,%1,%2,%3}, {%4,%5,%6,%7}, {%8,%9}, {%0,%1,%2,%3};\n"
        : "+f"(c[0]), "+f"(c[1]), "+f"(c[2]), "+f"(c[3])
        : "r"(a0), "r"(a1), "r"(a2), "r"(a3), "r"(b0), "r"(b1));
}
__device__ __forceinline__ void cp_async16(uint32_t dst_smem, const float* src) {
    asm volatile("cp.async.cg.shared.global [%0], [%1], 16;\n"
                 :: "r"(dst_smem), "l"(src));
}

__global__ void __launch_bounds__(NTHREADS, 2)
attn_bias_kernel(const float* __restrict__ x1,
                 const float* __restrict__ x2,
                 const float* __restrict__ x3,
                 const float* __restrict__ x4,
                 float* __restrict__ out) {
    const int mt = blockIdx.x;   // 0..15
    const int h  = blockIdx.y;   // 0..7
    const int b  = blockIdx.z;   // 0..1

    const int tid  = threadIdx.x;
    const int warp = tid >> 5;
    const int lane = tid & 31;
    const int r = lane >> 2;
    const int q = lane & 3;

    extern __shared__ uint32_t smem[];
    const uint32_t sb = (uint32_t)__cvta_generic_to_shared(smem);
    uint32_t* sQ  = smem + OQ;
    uint32_t* sKf = smem + OKF;
    uint32_t* sVT = smem + OVT;
    const float* sPBf = reinterpret_cast<const float*>(smem + OPB);
    const float* rawK = reinterpret_cast<const float*>(smem + ORK);
    const float* rawV = reinterpret_cast<const float*>(smem + ORV);

    // ---- stage Q once: fp16, pre-scaled by 0.125*log2e ----
    const float qs = 0.125f * LOG2E;
    const int srowK = tid >> 4;          // 0..7
    const int sc4   = tid & 15;          // 0..15
    const float* qbase = x1 + ((size_t)b * S_ + (size_t)mt * TM) * D_;
    #pragma unroll
    for (int j = 0; j < 16; ++j) {
        int row = srowK + 8 * j;
        float4 v = *reinterpret_cast<const float4*>(qbase + row * D_ + 4 * sc4);
        uint2 o;
        o.x = pack_h2(v.x * qs, v.y * qs);
        o.y = pack_h2(v.z * qs, v.w * qs);
        *reinterpret_cast<uint2*>(sQ + row * PQW + 2 * sc4) = o;
    }

    float accO[2][8][4];
    #pragma unroll
    for (int mf = 0; mf < 2; ++mf)
        #pragma unroll
        for (int n = 0; n < 8; ++n)
            #pragma unroll
            for (int j = 0; j < 4; ++j) accO[mf][n][j] = 0.0f;
    float lsum[2][2] = {{0.0f, 0.0f}, {0.0f, 0.0f}};

    const int R0 = warp * 32;

    // ---- staging pointers ----
    const float* kcp = x2 + (size_t)b * S_ * D_ + (size_t)srowK * D_ + sc4 * 4;
    const float* vcp = x4 + (size_t)b * S_ * D_ + (size_t)srowK * D_ + sc4 * 4;
    const uint32_t rkd = sb + 4u * (uint32_t)(ORK + srowK * PRW + 4 * sc4);
    const uint32_t rvd = sb + 4u * (uint32_t)(ORV + srowK * PRW + 4 * sc4);
    // bias: warp-local rows (R9-verified pattern)
    const int brow0 = warp * 32 + (lane >> 4);
    const int bc4   = lane & 15;
    const float* bptr = x3 + (((size_t)b * H_ + h) * S_ + (size_t)mt * TM + brow0) * S_
                        + bc4 * 4;
    const uint32_t sPB_b = sb + 4u * (uint32_t)(OPB + brow0 * PPW + 4 * bc4);
    // V transpose-convert geometry (reads raw smem)
    const int tp = tid >> 2;             // 0..31
    const int dq = tid & 3;              // 0..3
    const uint32_t vxor = (uint32_t)(tp ^ (dq << 3));

    // ---- prologue: raw K/V tile 0 in flight ----
    #pragma unroll
    for (int j = 0; j < 8; ++j) {
        cp_async16(rkd + 4u * (uint32_t)(8 * j * PRW), kcp + (size_t)(8 * j) * D_);
        cp_async16(rvd + 4u * (uint32_t)(8 * j * PRW), vcp + (size_t)(8 * j) * D_);
    }
    asm volatile("cp.async.commit_group;\n" ::: "memory");
    kcp += (size_t)TN * D_;
    vcp += (size_t)TN * D_;

    for (int it = 0; it < NITER; ++it) {
        // ---- raw(it) complete (only pending group at loop top) ----
        asm volatile("cp.async.wait_group 0;\n" ::: "memory");
        __syncthreads();   // raw visible to all; prev iter fully consumed

        // ---- bias tile cp.async (overlaps convert + QK) ----
        #pragma unroll
        for (int j = 0; j < 16; ++j)
            cp_async16(sPB_b + (uint32_t)(2 * j * PPW) * 4, bptr + (size_t)(2 * j) * S_);
        asm volatile("cp.async.commit_group;\n" ::: "memory");
        bptr += TN;

        // ---- convert raw -> fp16 K tile ----
        #pragma unroll
        for (int j = 0; j < 8; ++j) {
            int row = srowK + 8 * j;
            float4 v = *reinterpret_cast<const float4*>(rawK + row * PRW + 4 * sc4);
            uint2 o;
            o.x = pack_h2(v.x, v.y);
            o.y = pack_h2(v.z, v.w);
            *reinterpret_cast<uint2*>(sKf + row * PKW + 2 * sc4) = o;
        }
        // ---- convert raw -> fp16 V^T tile (xor-swizzled, pairs along t) ----
        #pragma unroll
        for (int jj = 0; jj < 4; ++jj) {
            float4 va = *reinterpret_cast<const float4*>(rawV + (2 * tp) * PRW + 16 * dq + 4 * jj);
            float4 vb = *reinterpret_cast<const float4*>(rawV + (2 * tp + 1) * PRW + 16 * dq + 4 * jj);
            int d0 = 16 * dq + 4 * jj;
            sVT[(d0 + 0) * PVW + vxor] = pack_h2(va.x, vb.x);
            sVT[(d0 + 1) * PVW + vxor] = pack_h2(va.y, vb.y);
            sVT[(d0 + 2) * PVW + vxor] = pack_h2(va.z, vb.z);
            sVT[(d0 + 3) * PVW + vxor] = pack_h2(va.w, vb.w);
        }
        __syncthreads();   // fp16 tiles visible; raw buffer free

        // ---- issue raw K/V(it+1) into the (now converted) raw buffer ----
        if (it + 1 < NITER) {
            #pragma unroll
            for (int j = 0; j < 8; ++j) {
                cp_async16(rkd + 4u * (uint32_t)(8 * j * PRW), kcp + (size_t)(8 * j) * D_);
                cp_async16(rvd + 4u * (uint32_t)(8 * j * PRW), vcp + (size_t)(8 * j) * D_);
            }
            asm volatile("cp.async.commit_group;\n" ::: "memory");
            kcp += (size_t)TN * D_;
            vcp += (size_t)TN * D_;
        }

        // ---- QK: S = Q @ K^T, fp16 m16n8k16, 4 k-steps over d ----
        float c[2][8][4];
        #pragma unroll
        for (int mf = 0; mf < 2; ++mf)
            #pragma unroll
            for (int n = 0; n < 8; ++n)
                #pragma unroll
                for (int j = 0; j < 4; ++j) c[mf][n][j] = 0.0f;

        #pragma unroll
        for (int k = 0; k < 4; ++k) {
            uint32_t a[2][4];
            #pragma unroll
            for (int mf = 0; mf < 2; ++mf) {
                const uint32_t* qrow0 = sQ + (R0 + 16 * mf + r) * PQW + 8 * k + q;
                const uint32_t* qrow1 = sQ + (R0 + 16 * mf + r + 8) * PQW + 8 * k + q;
                a[mf][0] = qrow0[0];
                a[mf][1] = qrow1[0];
                a[mf][2] = qrow0[4];
                a[mf][3] = qrow1[4];
            }
            #pragma unroll
            for (int n = 0; n < 8; ++n) {
                const uint32_t* krow = sKf + (8 * n + r) * PKW + 8 * k + q;
                uint32_t b0 = krow[0];
                uint32_t b1 = krow[4];
                mma_f16(c[0][n], a[0][0], a[0][1], a[0][2], a[0][3], b0, b1);
                mma_f16(c[1][n], a[1][0], a[1][1], a[1][2], a[1][3], b0, b1);
            }
        }

        // ---- bias ready (raw(it+1) may still be pending) ----
        if (it + 1 < NITER) {
            asm volatile("cp.async.wait_group 1;\n" ::: "memory");
        } else {
            asm volatile("cp.async.wait_group 0;\n" ::: "memory");
        }
        __syncwarp();   // warp-local bias staging -> warp-local visibility

        // ---- softmax: exp2, P packed to fp16 registers ----
        uint32_t pk[2][8][2];
        #pragma unroll
        for (int mf = 0; mf < 2; ++mf) {
            const int R = R0 + 16 * mf;
            #pragma unroll
            for (int n = 0; n < 8; ++n) {
                float2 bb0 = *reinterpret_cast<const float2*>(sPBf + (R + r) * PPW + 8 * n + 2 * q);
                float2 bb1 = *reinterpret_cast<const float2*>(sPBf + (R + r + 8) * PPW + 8 * n + 2 * q);
                float p0 = ex2(fmaf(bb0.x, LOG2E, c[mf][n][0]));
                float p1 = ex2(fmaf(bb0.y, LOG2E, c[mf][n][1]));
                float p2 = ex2(fmaf(bb1.x, LOG2E, c[mf][n][2]));
                float p3 = ex2(fmaf(bb1.y, LOG2E, c[mf][n][3]));
                lsum[mf][0] += p0 + p1;
                lsum[mf][1] += p2 + p3;
                pk[mf][n][0] = pack_h2(p0, p1);
                pk[mf][n][1] = pack_h2(p2, p3);
            }
        }

        // ---- PV: O += P @ V ; A from registers, B from sVT ----
        #pragma unroll
        for (int n = 0; n < 8; ++n) {
            const int d = 8 * n + r;
            const uint32_t f = (uint32_t)(((d >> 4) & 3) << 3);
            const uint32_t* vrow = sVT + d * PVW;
            #pragma unroll
            for (int k = 0; k < 4; ++k) {
                uint32_t b0 = vrow[(uint32_t)(8 * k + q) ^ f];
                uint32_t b1 = vrow[(uint32_t)(8 * k + q + 4) ^ f];
                mma_f16(accO[0][n], pk[0][2*k][0], pk[0][2*k][1],
                                    pk[0][2*k+1][0], pk[0][2*k+1][1], b0, b1);
                mma_f16(accO[1][n], pk[1][2*k][0], pk[1][2*k][1],
                                    pk[1][2*k+1][0], pk[1][2*k+1][1], b0, b1);
            }
        }
    }

    // ---- finalize: quad-reduce row sums, divide, store ----
    #pragma unroll
    for (int mf = 0; mf < 2; ++mf)
        #pragma unroll
        for (int j = 0; j < 2; ++j) {
            lsum[mf][j] += __shfl_xor_sync(0xffffffffu, lsum[mf][j], 1);
            lsum[mf][j] += __shfl_xor_sync(0xffffffffu, lsum[mf][j], 2);
        }

    float inv[2][2];
    inv[0][0] = 1.0f / lsum[0][0]; inv[0][1] = 1.0f / lsum[0][1];
    inv[1][0] = 1.0f / lsum[1][0]; inv[1][1] = 1.0f / lsum[1][1];

    float* obase = out + (((size_t)b * H_ + h) * S_ + (size_t)mt * TM) * D_;
    #pragma unroll
    for (int mf = 0; mf < 2; ++mf) {
        const int R = R0 + 16 * mf;
        #pragma unroll
        for (int n = 0; n < 8; ++n) {
            float2 v0 = make_float2(accO[mf][n][0] * inv[mf][0], accO[mf][n][1] * inv[mf][0]);
            float2 v1 = make_float2(accO[mf][n][2] * inv[mf][1], accO[mf][n][3] * inv[mf][1]);
            *reinterpret_cast<float2*>(obase + (size_t)(R + r) * D_ + 8 * n + 2 * q) = v0;
            *reinterpret_cast<float2*>(obase + (size_t)(R + r + 8) * D_ + 8 * n + 2 * q) = v1;
        }
    }
}

extern "C" void kernel_launch(void* const* d_in, const int* in_sizes, int n_in,
                              void* d_out, int out_size) {
    (void)in_sizes; (void)n_in; (void)out_size;
    const float* x1 = (const float*)d_in[0];
    const float* x2 = (const float*)d_in[1];
    const float* x3 = (const float*)d_in[2];
    const float* x4 = (const float*)d_in[3];
    float* out = (float*)d_out;

    cudaFuncSetAttribute(attn_bias_kernel,
                         cudaFuncAttributeMaxDynamicSharedMemorySize, SMEM_BYTES);

    dim3 grid(S_ / TM, H_, B_);   // 16 x 8 x 2 = 256 CTAs
    attn_bias_kernel<<<grid, NTHREADS, SMEM_BYTES>>>(x1, x2, x3, x4, out);
}

// round 14
// speedup vs baseline: 1.6126x; 1.0308x over previous
#include <cuda_runtime.h>
#include <cuda_fp16.h>
#include <cstdint>
#include <cstddef>

#define B_ 2
#define S_ 2048
#define D_ 64
#define H_ 8

#define TM 128
#define TN 64
#define NTHREADS 128
#define NITER (S_ / TN)

// pitches in 32-bit words
#define PQW 36   // Q fp16 pairs
#define PKW 36   // K fp16 pairs
#define PVW 36   // V^T fp16 pairs
#define PPW 72   // bias fp32
#define PRW 68   // raw fp32 K/V staging

// smem word offsets
#define OQ   0
#define OKF  (OQ  + TM*PQW)
#define OVT  (OKF + TN*PKW)
#define OPB  (OVT + TN*PVW)
#define ORK  (OPB + TM*PPW)
#define ORV  (ORK + TN*PRW)
#define SMEM_WORDS (ORV + TN*PRW)
#define SMEM_BYTES (SMEM_WORDS * 4)   // 108,544 B -> 2 CTAs/SM

#define LOG2E 1.4426950408889634f
#define ONES_H2 0x3C003C00u          // fp16x2 {1.0, 1.0}

__device__ __forceinline__ uint32_t pack_h2(float lo, float hi) {
    uint32_t d;
    asm("cvt.rn.f16x2.f32 %0, %1, %2;" : "=r"(d) : "f"(hi), "f"(lo));
    return d;
}
__device__ __forceinline__ uint32_t ex2h2(uint32_t x) {
    uint32_t r;
    asm("ex2.approx.f16x2 %0, %1;" : "=r"(r) : "r"(x));
    return r;
}
__device__ __forceinline__ void mma_f16(float c[4],
                                        uint32_t a0, uint32_t a1, uint32_t a2, uint32_t a3,
                                        uint32_t b0, uint32_t b1) {
    asm volatile(
        "mma.sync.aligned.m16n8k16.row.col.f32.f16.f16.f32 "
        "{%0,%1,%2,%3}, {%4,%5,%6,%7}, {%8,%9}, {%0,%1,%2,%3};\n"
        : "+f"(c[0]), "+f"(c[1]), "+f"(c[2]), "+f"(c[3])
        : "r"(a0), "r"(a1), "r"(a2), "r"(a3), "r"(b0), "r"(b1));
}
__device__ __forceinline__ void cp_async16(uint32_t dst_smem, const float* src) {
    asm volatile("cp.async.cg.shared.global [%0], [%1], 16;\n"
                 :: "r"(dst_smem), "l"(src));
}

__global__ void __launch_bounds__(NTHREADS, 2)
attn_bias_kernel(const float* __restrict__ x1,
                 const float* __restrict__ x2,
                 const float* __restrict__ x3,
                 const float* __restrict__ x4,
                 float* __restrict__ out) {
    const int mt = blockIdx.x;   // 0..15
    const int h  = blockIdx.y;   // 0..7
    const int b  = blockIdx.z;   // 0..1

    const int tid  = threadIdx.x;
    const int warp = tid >> 5;
    const int lane = tid & 31;
    const int r = lane >> 2;
    const int q = lane & 3;

    extern __shared__ uint32_t smem[];
    const uint32_t sb = (uint32_t)__cvta_generic_to_shared(smem);
    uint32_t* sQ  = smem + OQ;
    uint32_t* sKf = smem + OKF;
    uint32_t* sVT = smem + OVT;
    const float* sPBf = reinterpret_cast<const float*>(smem + OPB);
    const float* rawK = reinterpret_cast<const float*>(smem + ORK);
    const float* rawV = reinterpret_cast<const float*>(smem + ORV);

    // ---- stage Q once: fp16, pre-scaled by 0.125*log2e ----
    const float qs = 0.125f * LOG2E;
    const int srowK = tid >> 4;          // 0..7
    const int sc4   = tid & 15;          // 0..15
    const float* qbase = x1 + ((size_t)b * S_ + (size_t)mt * TM) * D_;
    #pragma unroll
    for (int j = 0; j < 16; ++j) {
        int row = srowK + 8 * j;
        float4 v = *reinterpret_cast<const float4*>(qbase + row * D_ + 4 * sc4);
        uint2 o;
        o.x = pack_h2(v.x * qs, v.y * qs);
        o.y = pack_h2(v.z * qs, v.w * qs);
        *reinterpret_cast<uint2*>(sQ + row * PQW + 2 * sc4) = o;
    }

    float accO[2][8][4];
    #pragma unroll
    for (int mf = 0; mf < 2; ++mf)
        #pragma unroll
        for (int n = 0; n < 8; ++n)
            #pragma unroll
            for (int j = 0; j < 4; ++j) accO[mf][n][j] = 0.0f;
    // row-sum accumulators via tensor core (B = ones)
    float accS[2][4];
    #pragma unroll
    for (int mf = 0; mf < 2; ++mf)
        #pragma unroll
        for (int j = 0; j < 4; ++j) accS[mf][j] = 0.0f;

    const int R0 = warp * 32;

    // ---- staging pointers ----
    const float* kcp = x2 + (size_t)b * S_ * D_ + (size_t)srowK * D_ + sc4 * 4;
    const float* vcp = x4 + (size_t)b * S_ * D_ + (size_t)srowK * D_ + sc4 * 4;
    const uint32_t rkd = sb + 4u * (uint32_t)(ORK + srowK * PRW + 4 * sc4);
    const uint32_t rvd = sb + 4u * (uint32_t)(ORV + srowK * PRW + 4 * sc4);
    const int brow0 = warp * 32 + (lane >> 4);
    const int bc4   = lane & 15;
    const float* bptr = x3 + (((size_t)b * H_ + h) * S_ + (size_t)mt * TM + brow0) * S_
                        + bc4 * 4;
    const uint32_t sPB_b = sb + 4u * (uint32_t)(OPB + brow0 * PPW + 4 * bc4);
    const int tp = tid >> 2;             // 0..31
    const int dq = tid & 3;              // 0..3
    const uint32_t vxor = (uint32_t)(tp ^ (dq << 3));

    // ---- prologue: raw K/V tile 0 in flight ----
    #pragma unroll
    for (int j = 0; j < 8; ++j) {
        cp_async16(rkd + 4u * (uint32_t)(8 * j * PRW), kcp + (size_t)(8 * j) * D_);
        cp_async16(rvd + 4u * (uint32_t)(8 * j * PRW), vcp + (size_t)(8 * j) * D_);
    }
    asm volatile("cp.async.commit_group;\n" ::: "memory");
    kcp += (size_t)TN * D_;
    vcp += (size_t)TN * D_;

    for (int it = 0; it < NITER; ++it) {
        // ---- raw(it) complete ----
        asm volatile("cp.async.wait_group 0;\n" ::: "memory");
        __syncthreads();

        // ---- bias tile cp.async (overlaps convert + QK) ----
        #pragma unroll
        for (int j = 0; j < 16; ++j)
            cp_async16(sPB_b + (uint32_t)(2 * j * PPW) * 4, bptr + (size_t)(2 * j) * S_);
        asm volatile("cp.async.commit_group;\n" ::: "memory");
        bptr += TN;

        // ---- convert raw -> fp16 K tile ----
        #pragma unroll
        for (int j = 0; j < 8; ++j) {
            int row = srowK + 8 * j;
            float4 v = *reinterpret_cast<const float4*>(rawK + row * PRW + 4 * sc4);
            uint2 o;
            o.x = pack_h2(v.x, v.y);
            o.y = pack_h2(v.z, v.w);
            *reinterpret_cast<uint2*>(sKf + row * PKW + 2 * sc4) = o;
        }
        // ---- convert raw -> fp16 V^T tile (xor-swizzled, pairs along t) ----
        #pragma unroll
        for (int jj = 0; jj < 4; ++jj) {
            float4 va = *reinterpret_cast<const float4*>(rawV + (2 * tp) * PRW + 16 * dq + 4 * jj);
            float4 vb = *reinterpret_cast<const float4*>(rawV + (2 * tp + 1) * PRW + 16 * dq + 4 * jj);
            int d0 = 16 * dq + 4 * jj;
            sVT[(d0 + 0) * PVW + vxor] = pack_h2(va.x, vb.x);
            sVT[(d0 + 1) * PVW + vxor] = pack_h2(va.y, vb.y);
            sVT[(d0 + 2) * PVW + vxor] = pack_h2(va.z, vb.z);
            sVT[(d0 + 3) * PVW + vxor] = pack_h2(va.w, vb.w);
        }
        __syncthreads();   // fp16 tiles visible; raw buffer free

        // ---- issue raw K/V(it+1) ----
        if (it + 1 < NITER) {
            #pragma unroll
            for (int j = 0; j < 8; ++j) {
                cp_async16(rkd + 4u * (uint32_t)(8 * j * PRW), kcp + (size_t)(8 * j) * D_);
                cp_async16(rvd + 4u * (uint32_t)(8 * j * PRW), vcp + (size_t)(8 * j) * D_);
            }
            asm volatile("cp.async.commit_group;\n" ::: "memory");
            kcp += (size_t)TN * D_;
            vcp += (size_t)TN * D_;
        }

        // ---- QK: S = Q @ K^T, fp16 m16n8k16, 4 k-steps over d ----
        float c[2][8][4];
        #pragma unroll
        for (int mf = 0; mf < 2; ++mf)
            #pragma unroll
            for (int n = 0; n < 8; ++n)
                #pragma unroll
                for (int j = 0; j < 4; ++j) c[mf][n][j] = 0.0f;

        #pragma unroll
        for (int k = 0; k < 4; ++k) {
            uint32_t a[2][4];
            #pragma unroll
            for (int mf = 0; mf < 2; ++mf) {
                const uint32_t* qrow0 = sQ + (R0 + 16 * mf + r) * PQW + 8 * k + q;
                const uint32_t* qrow1 = sQ + (R0 + 16 * mf + r + 8) * PQW + 8 * k + q;
                a[mf][0] = qrow0[0];
                a[mf][1] = qrow1[0];
                a[mf][2] = qrow0[4];
                a[mf][3] = qrow1[4];
            }
            #pragma unroll
            for (int n = 0; n < 8; ++n) {
                const uint32_t* krow = sKf + (8 * n + r) * PKW + 8 * k + q;
                uint32_t b0 = krow[0];
                uint32_t b1 = krow[4];
                mma_f16(c[0][n], a[0][0], a[0][1], a[0][2], a[0][3], b0, b1);
                mma_f16(c[1][n], a[1][0], a[1][1], a[1][2], a[1][3], b0, b1);
            }
        }

        // ---- bias ready ----
        if (it + 1 < NITER) {
            asm volatile("cp.async.wait_group 1;\n" ::: "memory");
        } else {
            asm volatile("cp.async.wait_group 0;\n" ::: "memory");
        }
        __syncwarp();

        // ---- softmax: pack log2-logits to fp16x2, ex2.approx.f16x2 ----
        uint32_t pk[2][8][2];
        #pragma unroll
        for (int mf = 0; mf < 2; ++mf) {
            const int R = R0 + 16 * mf;
            #pragma unroll
            for (int n = 0; n < 8; ++n) {
                float2 bb0 = *reinterpret_cast<const float2*>(sPBf + (R + r) * PPW + 8 * n + 2 * q);
                float2 bb1 = *reinterpret_cast<const float2*>(sPBf + (R + r + 8) * PPW + 8 * n + 2 * q);
                float e0 = fmaf(bb0.x, LOG2E, c[mf][n][0]);
                float e1 = fmaf(bb0.y, LOG2E, c[mf][n][1]);
                float e2 = fmaf(bb1.x, LOG2E, c[mf][n][2]);
                float e3 = fmaf(bb1.y, LOG2E, c[mf][n][3]);
                pk[mf][n][0] = ex2h2(pack_h2(e0, e1));
                pk[mf][n][1] = ex2h2(pack_h2(e2, e3));
            }
        }

        // ---- PV: O += P @ V ; row sums via B = ones (no LDS) ----
        #pragma unroll
        for (int k = 0; k < 4; ++k) {
            mma_f16(accS[0], pk[0][2*k][0], pk[0][2*k][1],
                             pk[0][2*k+1][0], pk[0][2*k+1][1], ONES_H2, ONES_H2);
            mma_f16(accS[1], pk[1][2*k][0], pk[1][2*k][1],
                             pk[1][2*k+1][0], pk[1][2*k+1][1], ONES_H2, ONES_H2);
        }
        #pragma unroll
        for (int n = 0; n < 8; ++n) {
            const int d = 8 * n + r;
            const uint32_t f = (uint32_t)(((d >> 4) & 3) << 3);
            const uint32_t* vrow = sVT + d * PVW;
            #pragma unroll
            for (int k = 0; k < 4; ++k) {
                uint32_t b0 = vrow[(uint32_t)(8 * k + q) ^ f];
                uint32_t b1 = vrow[(uint32_t)(8 * k + q + 4) ^ f];
                mma_f16(accO[0][n], pk[0][2*k][0], pk[0][2*k][1],
                                    pk[0][2*k+1][0], pk[0][2*k+1][1], b0, b1);
                mma_f16(accO[1][n], pk[1][2*k][0], pk[1][2*k][1],
                                    pk[1][2*k+1][0], pk[1][2*k+1][1], b0, b1);
            }
        }
    }

    // ---- finalize: row sums already reduced by the ones-MMA ----
    float inv[2][2];
    inv[0][0] = 1.0f / accS[0][0]; inv[0][1] = 1.0f / accS[0][2];
    inv[1][0] = 1.0f / accS[1][0]; inv[1][1] = 1.0f / accS[1][2];

    float* obase = out + (((size_t)b * H_ + h) * S_ + (size_t)mt * TM) * D_;
    #pragma unroll
    for (int mf = 0; mf < 2; ++mf) {
        const int R = R0 + 16 * mf;
        #pragma unroll
        for (int n = 0; n < 8; ++n) {
            float2 v0 = make_float2(accO[mf][n][0] * inv[mf][0], accO[mf][n][1] * inv[mf][0]);
            float2 v1 = make_float2(accO[mf][n][2] * inv[mf][1], accO[mf][n][3] * inv[mf][1]);
            *reinterpret_cast<float2*>(obase + (size_t)(R + r) * D_ + 8 * n + 2 * q) = v0;
            *reinterpret_cast<float2*>(obase + (size_t)(R + r + 8) * D_ + 8 * n + 2 * q) = v1;
        }
    }
}

extern "C" void kernel_launch(void* const* d_in, const int* in_sizes, int n_in,
                              void* d_out, int out_size) {
    (void)in_sizes; (void)n_in; (void)out_size;
    const float* x1 = (const float*)d_in[0];
    const float* x2 = (const float*)d_in[1];
    const float* x3 = (const float*)d_in[2];
    const float* x4 = (const float*)d_in[3];
    float* out = (float*)d_out;

    cudaFuncSetAttribute(attn_bias_kernel,
                         cudaFuncAttributeMaxDynamicSharedMemorySize, SMEM_BYTES);

    dim3 grid(S_ / TM, H_, B_);   // 16 x 8 x 2 = 256 CTAs
    attn_bias_kernel<<<grid, NTHREADS, SMEM_BYTES>>>(x1, x2, x3, x4, out);
}

// round 15
// speedup vs baseline: 2.0343x; 1.2615x over previous
#include <cuda_runtime.h>
#include <cuda_fp16.h>
#include <cstdint>
#include <cstddef>

#define B_ 2
#define S_ 2048
#define D_ 64
#define H_ 8

#define TM 128
#define TN 64
#define NTHREADS 128
#define NITER (S_ / TN)
#define NTILE NITER

// pitches in 32-bit words
#define PQW 36   // Q fp16 pairs
#define PKW 36   // K fp16 pairs
#define PVW 36   // V^T fp16 pairs
#define PPW 72   // bias fp32

// smem word offsets (main kernel)
#define OQ   0
#define OK0  (OQ  + TM*PQW)    // 4608
#define OK1  (OK0 + TN*PKW)    // 6912
#define OV0  (OK1 + TN*PKW)    // 9216
#define OV1  (OV0 + TN*PVW)    // 11520
#define OPB  (OV1 + TN*PVW)    // 13824
#define SMEM_WORDS (OPB + TM*PPW)
#define SMEM_BYTES (SMEM_WORDS * 4)   // 92,160 B -> 2 CTAs/SM

#define LOG2E 1.4426950408889634f
#define ONES_H2 0x3C003C00u           // fp16x2 {1.0, 1.0}
#define EOFF (-8.0f)                  // log2-domain offset (cancels in normalization)

// pre-converted fp16 operands (written by prep kernels each launch)
__device__ uint32_t gK16[B_][NTILE][TN * 32];   // [tile][row t][32 words of d-pairs]
__device__ uint32_t gVT16[B_][NTILE][TN * 32];  // [tile][row d][32 swizzled t-pair words]

__device__ __forceinline__ uint32_t pack_h2(float lo, float hi) {
    uint32_t d;
    asm("cvt.rn.f16x2.f32 %0, %1, %2;" : "=r"(d) : "f"(hi), "f"(lo));
    return d;
}
__device__ __forceinline__ uint32_t ex2h2(uint32_t x) {
    uint32_t r;
    asm("ex2.approx.f16x2 %0, %1;" : "=r"(r) : "r"(x));
    return r;
}
__device__ __forceinline__ void mma_f16(float c[4],
                                        uint32_t a0, uint32_t a1, uint32_t a2, uint32_t a3,
                                        uint32_t b0, uint32_t b1) {
    asm volatile(
        "mma.sync.aligned.m16n8k16.row.col.f32.f16.f16.f32 "
        "{%0,%1,%2,%3}, {%4,%5,%6,%7}, {%8,%9}, {%0,%1,%2,%3};\n"
        : "+f"(c[0]), "+f"(c[1]), "+f"(c[2]), "+f"(c[3])
        : "r"(a0), "r"(a1), "r"(a2), "r"(a3), "r"(b0), "r"(b1));
}
__device__ __forceinline__ void cp_async16(uint32_t dst_smem, const void* src) {
    asm volatile("cp.async.cg.shared.global [%0], [%1], 16;\n"
                 :: "r"(dst_smem), "l"(src));
}

// ---- prep: x2 -> fp16 K tiles (pairs along d, row-major [t][d]) ----
__global__ void prep_k_kernel(const float* __restrict__ x2) {
    const int tile = blockIdx.x, b = blockIdx.y;
    const int tid = threadIdx.x;
    const float* src = x2 + ((size_t)b * S_ + (size_t)tile * TN) * D_;
    uint32_t* dst = gK16[b][tile];
    #pragma unroll
    for (int j = 0; j < 8; ++j) {
        int idx = tid + 128 * j;
        int row = idx >> 4, c4 = idx & 15;
        float4 v = *reinterpret_cast<const float4*>(src + row * D_ + 4 * c4);
        dst[row * 32 + 2 * c4]     = pack_h2(v.x, v.y);
        dst[row * 32 + 2 * c4 + 1] = pack_h2(v.z, v.w);
    }
}

// ---- prep: x4 -> fp16 V^T tiles (pairs along t, xor-swizzled rows) ----
__global__ void prep_v_kernel(const float* __restrict__ x4) {
    const int tile = blockIdx.x, b = blockIdx.y;
    const int tid = threadIdx.x;
    __shared__ float raw[TN * 68];
    const float* src = x4 + ((size_t)b * S_ + (size_t)tile * TN) * D_;
    #pragma unroll
    for (int j = 0; j < 8; ++j) {
        int idx = tid + 128 * j;
        int row = idx >> 4, c4 = idx & 15;
        float4 v = *reinterpret_cast<const float4*>(src + row * D_ + 4 * c4);
        *reinterpret_cast<float4*>(raw + row * 68 + 4 * c4) = v;
    }
    __syncthreads();
    uint32_t* dst = gVT16[b][tile];
    #pragma unroll
    for (int j = 0; j < 16; ++j) {
        int idx = tid + 128 * j;
        int d = idx >> 5, w = idx & 31;
        int f = ((d >> 4) & 3) << 3;
        int tp = w ^ f;
        dst[d * 32 + w] = pack_h2(raw[(2 * tp) * 68 + d], raw[(2 * tp + 1) * 68 + d]);
    }
}

__global__ void __launch_bounds__(NTHREADS, 2)
attn_bias_kernel(const float* __restrict__ x1,
                 const float* __restrict__ x3,
                 float* __restrict__ out) {
    const int mt = blockIdx.x;   // 0..15
    const int h  = blockIdx.y;   // 0..7
    const int b  = blockIdx.z;   // 0..1

    const int tid  = threadIdx.x;
    const int warp = tid >> 5;
    const int lane = tid & 31;
    const int r = lane >> 2;
    const int q = lane & 3;

    extern __shared__ uint32_t smem[];
    const uint32_t sb = (uint32_t)__cvta_generic_to_shared(smem);
    uint32_t* sQ = smem + OQ;
    const float* sPBf = reinterpret_cast<const float*>(smem + OPB);

    // ---- stage Q once: fp16, pre-scaled by 0.125*log2e ----
    const float qs = 0.125f * LOG2E;
    const int srowK = tid >> 4;          // 0..7
    const int sc4   = tid & 15;          // 0..15
    const float* qbase = x1 + ((size_t)b * S_ + (size_t)mt * TM) * D_;
    #pragma unroll
    for (int j = 0; j < 16; ++j) {
        int row = srowK + 8 * j;
        float4 v = *reinterpret_cast<const float4*>(qbase + row * D_ + 4 * sc4);
        uint2 o;
        o.x = pack_h2(v.x * qs, v.y * qs);
        o.y = pack_h2(v.z * qs, v.w * qs);
        *reinterpret_cast<uint2*>(sQ + row * PQW + 2 * sc4) = o;
    }

    float accO[2][8][4];
    #pragma unroll
    for (int mf = 0; mf < 2; ++mf)
        #pragma unroll
        for (int n = 0; n < 8; ++n)
            #pragma unroll
            for (int j = 0; j < 4; ++j) accO[mf][n][j] = 0.0f;
    float accS[2][4];
    #pragma unroll
    for (int mf = 0; mf < 2; ++mf)
        #pragma unroll
        for (int j = 0; j < 4; ++j) accS[mf][j] = 0.0f;

    const int R0 = warp * 32;

    // ---- staging geometry ----
    // K/VT tile copy: 512 16B-chunks, 4/thread; chunk ch = tid + 128j
    // smem dst: row = ch>>3 (pitch 36 words), col = (ch&7)*4 words
    const uint32_t kv_dst_off = 4u * (uint32_t)((tid >> 3) * 36 + (tid & 7) * 4);
    const uint32_t kv_dst_step = 4u * (uint32_t)(16 * 36);   // +16 rows per j
    const uint32_t* gk_src0 = gK16[b][0] + tid * 4;          // +512 words per j
    const uint32_t* gv_src0 = gVT16[b][0] + tid * 4;
    // bias: warp-local rows
    const int brow0 = warp * 32 + (lane >> 4);
    const int bc4   = lane & 15;
    const float* bptr = x3 + (((size_t)b * H_ + h) * S_ + (size_t)mt * TM + brow0) * S_
                        + bc4 * 4;
    const uint32_t sPB_b = sb + 4u * (uint32_t)(OPB + brow0 * PPW + 4 * bc4);

    // ---- prologue: kv(0) then bias(0) (commit order is load-bearing) ----
    {
        const uint32_t dk = sb + 4u * (uint32_t)OK0 + kv_dst_off;
        const uint32_t dv = sb + 4u * (uint32_t)OV0 + kv_dst_off;
        #pragma unroll
        for (int j = 0; j < 4; ++j) {
            cp_async16(dk + j * kv_dst_step, gk_src0 + j * 512);
            cp_async16(dv + j * kv_dst_step, gv_src0 + j * 512);
        }
        asm volatile("cp.async.commit_group;\n" ::: "memory");
    }
    #pragma unroll
    for (int j = 0; j < 16; ++j)
        cp_async16(sPB_b + (uint32_t)(2 * j * PPW) * 4, bptr + (size_t)(2 * j) * S_);
    asm volatile("cp.async.commit_group;\n" ::: "memory");
    bptr += TN;

    for (int it = 0; it < NITER; ++it) {
        // ---- kv(it) complete (oldest pending group) ----
        asm volatile("cp.async.wait_group 1;\n" ::: "memory");
        __syncthreads();   // kv(it) visible; prev buffers fully consumed

        // ---- issue kv(it+1) into the other buffer ----
        if (it + 1 < NITER) {
            const uint32_t ok = ((it + 1) & 1) ? (uint32_t)OK1 : (uint32_t)OK0;
            const uint32_t ov = ((it + 1) & 1) ? (uint32_t)OV1 : (uint32_t)OV0;
            const uint32_t dk = sb + 4u * ok + kv_dst_off;
            const uint32_t dv = sb + 4u * ov + kv_dst_off;
            const uint32_t* gk = gk_src0 + (size_t)(it + 1) * (TN * 32);
            const uint32_t* gv = gv_src0 + (size_t)(it + 1) * (TN * 32);
            #pragma unroll
            for (int j = 0; j < 4; ++j) {
                cp_async16(dk + j * kv_dst_step, gk + j * 512);
                cp_async16(dv + j * kv_dst_step, gv + j * 512);
            }
            asm volatile("cp.async.commit_group;\n" ::: "memory");
        }

        const uint32_t* sKf = smem + ((it & 1) ? OK1 : OK0);
        const uint32_t* sVT = smem + ((it & 1) ? OV1 : OV0);

        // ---- QK: S = Q @ K^T (accumulator pre-biased by EOFF) ----
        float c[2][8][4];
        #pragma unroll
        for (int mf = 0; mf < 2; ++mf)
            #pragma unroll
            for (int n = 0; n < 8; ++n)
                #pragma unroll
                for (int j = 0; j < 4; ++j) c[mf][n][j] = EOFF;

        #pragma unroll
        for (int k = 0; k < 4; ++k) {
            uint32_t a[2][4];
            #pragma unroll
            for (int mf = 0; mf < 2; ++mf) {
                const uint32_t* qrow0 = sQ + (R0 + 16 * mf + r) * PQW + 8 * k + q;
                const uint32_t* qrow1 = sQ + (R0 + 16 * mf + r + 8) * PQW + 8 * k + q;
                a[mf][0] = qrow0[0];
                a[mf][1] = qrow1[0];
                a[mf][2] = qrow0[4];
                a[mf][3] = qrow1[4];
            }
            #pragma unroll
            for (int n = 0; n < 8; ++n) {
                const uint32_t* krow = sKf + (8 * n + r) * PKW + 8 * k + q;
                uint32_t b0 = krow[0];
                uint32_t b1 = krow[4];
                mma_f16(c[0][n], a[0][0], a[0][1], a[0][2], a[0][3], b0, b1);
                mma_f16(c[1][n], a[1][0], a[1][1], a[1][2], a[1][3], b0, b1);
            }
        }

        // ---- bias(it) ready ----
        if (it + 1 < NITER) {
            asm volatile("cp.async.wait_group 1;\n" ::: "memory");
        } else {
            asm volatile("cp.async.wait_group 0;\n" ::: "memory");
        }
        __syncwarp();

        // ---- softmax: fp16x2 exp2 of offset log2-logits ----
        uint32_t pk[2][8][2];
        #pragma unroll
        for (int mf = 0; mf < 2; ++mf) {
            const int R = R0 + 16 * mf;
            #pragma unroll
            for (int n = 0; n < 8; ++n) {
                float2 bb0 = *reinterpret_cast<const float2*>(sPBf + (R + r) * PPW + 8 * n + 2 * q);
                float2 bb1 = *reinterpret_cast<const float2*>(sPBf + (R + r + 8) * PPW + 8 * n + 2 * q);
                float e0 = fmaf(bb0.x, LOG2E, c[mf][n][0]);
                float e1 = fmaf(bb0.y, LOG2E, c[mf][n][1]);
                float e2 = fmaf(bb1.x, LOG2E, c[mf][n][2]);
                float e3 = fmaf(bb1.y, LOG2E, c[mf][n][3]);
                pk[mf][n][0] = ex2h2(pack_h2(e0, e1));
                pk[mf][n][1] = ex2h2(pack_h2(e2, e3));
            }
        }

        // ---- issue bias(it+1): warp-local rows already consumed ----
        if (it + 1 < NITER) {
            #pragma unroll
            for (int j = 0; j < 16; ++j)
                cp_async16(sPB_b + (uint32_t)(2 * j * PPW) * 4, bptr + (size_t)(2 * j) * S_);
            asm volatile("cp.async.commit_group;\n" ::: "memory");
            bptr += TN;
        }

        // ---- row sums via ones-MMA + PV ----
        #pragma unroll
        for (int k = 0; k < 4; ++k) {
            mma_f16(accS[0], pk[0][2*k][0], pk[0][2*k][1],
                             pk[0][2*k+1][0], pk[0][2*k+1][1], ONES_H2, ONES_H2);
            mma_f16(accS[1], pk[1][2*k][0], pk[1][2*k][1],
                             pk[1][2*k+1][0], pk[1][2*k+1][1], ONES_H2, ONES_H2);
        }
        #pragma unroll
        for (int n = 0; n < 8; ++n) {
            const int d = 8 * n + r;
            const uint32_t f = (uint32_t)(((d >> 4) & 3) << 3);
            const uint32_t* vrow = sVT + d * PVW;
            #pragma unroll
            for (int k = 0; k < 4; ++k) {
                uint32_t b0 = vrow[(uint32_t)(8 * k + q) ^ f];
                uint32_t b1 = vrow[(uint32_t)(8 * k + q + 4) ^ f];
                mma_f16(accO[0][n], pk[0][2*k][0], pk[0][2*k][1],
                                    pk[0][2*k+1][0], pk[0][2*k+1][1], b0, b1);
                mma_f16(accO[1][n], pk[1][2*k][0], pk[1][2*k][1],
                                    pk[1][2*k+1][0], pk[1][2*k+1][1], b0, b1);
            }
        }
    }

    // ---- finalize ----
    float inv[2][2];
    inv[0][0] = 1.0f / accS[0][0]; inv[0][1] = 1.0f / accS[0][2];
    inv[1][0] = 1.0f / accS[1][0]; inv[1][1] = 1.0f / accS[1][2];

    float* obase = out + (((size_t)b * H_ + h) * S_ + (size_t)mt * TM) * D_;
    #pragma unroll
    for (int mf = 0; mf < 2; ++mf) {
        const int R = R0 + 16 * mf;
        #pragma unroll
        for (int n = 0; n < 8; ++n) {
            float2 v0 = make_float2(accO[mf][n][0] * inv[mf][0], accO[mf][n][1] * inv[mf][0]);
            float2 v1 = make_float2(accO[mf][n][2] * inv[mf][1], accO[mf][n][3] * inv[mf][1]);
            *reinterpret_cast<float2*>(obase + (size_t)(R + r) * D_ + 8 * n + 2 * q) = v0;
            *reinterpret_cast<float2*>(obase + (size_t)(R + r + 8) * D_ + 8 * n + 2 * q) = v1;
        }
    }
}

extern "C" void kernel_launch(void* const* d_in, const int* in_sizes, int n_in,
                              void* d_out, int out_size) {
    (void)in_sizes; (void)n_in; (void)out_size;
    const float* x1 = (const float*)d_in[0];
    const float* x2 = (const float*)d_in[1];
    const float* x3 = (const float*)d_in[2];
    const float* x4 = (const float*)d_in[3];
    float* out = (float*)d_out;

    dim3 pgrid(NTILE, B_);
    prep_k_kernel<<<pgrid, 128>>>(x2);
    prep_v_kernel<<<pgrid, 128>>>(x4);

    cudaFuncSetAttribute(attn_bias_kernel,
                         cudaFuncAttributeMaxDynamicSharedMemorySize, SMEM_BYTES);

    dim3 grid(S_ / TM, H_, B_);   // 16 x 8 x 2 = 256 CTAs
    attn_bias_kernel<<<grid, NTHREADS, SMEM_BYTES>>>(x1, x3, out);
}

// round 16
// speedup vs baseline: 2.3305x; 1.1456x over previous
#include <cuda_runtime.h>
#include <cuda_fp16.h>
#include <cstdint>
#include <cstddef>

#define B_ 2
#define S_ 2048
#define D_ 64
#define H_ 8

#define TM 64            // rows per CTA
#define HPC 2            // heads per CTA
#define TN 64
#define NTHREADS 128
#define NITER (S_ / TN)
#define NTILE NITER

// pitches in 32-bit words
#define PQW 36   // Q fp16 pairs
#define PKW 36   // K fp16 pairs
#define PVW 36   // V^T fp16 pairs
#define PPW 72   // bias fp32

// smem word offsets (main kernel)
#define OQ   0
#define OK0  (OQ  + TM*PQW)        // 2304
#define OK1  (OK0 + TN*PKW)
#define OV0  (OK1 + TN*PKW)
#define OV1  (OV0 + TN*PVW)
#define OPB  (OV1 + TN*PVW)        // bias: [HPC][TM][PPW]
#define SMEM_WORDS (OPB + HPC*TM*PPW)
#define SMEM_BYTES (SMEM_WORDS * 4)   // 82,944 B -> 2 CTAs/SM

#define LOG2E 1.4426950408889634f
#define ONES_H2 0x3C003C00u
#define EOFF (-8.0f)

// pre-converted fp16 operands
__device__ uint32_t gK16[B_][NTILE][TN * 32];
__device__ uint32_t gVT16[B_][NTILE][TN * 32];

__device__ __forceinline__ uint32_t pack_h2(float lo, float hi) {
    uint32_t d;
    asm("cvt.rn.f16x2.f32 %0, %1, %2;" : "=r"(d) : "f"(hi), "f"(lo));
    return d;
}
__device__ __forceinline__ uint32_t ex2h2(uint32_t x) {
    uint32_t r;
    asm("ex2.approx.f16x2 %0, %1;" : "=r"(r) : "r"(x));
    return r;
}
__device__ __forceinline__ void mma_f16(float c[4],
                                        uint32_t a0, uint32_t a1, uint32_t a2, uint32_t a3,
                                        uint32_t b0, uint32_t b1) {
    asm volatile(
        "mma.sync.aligned.m16n8k16.row.col.f32.f16.f16.f32 "
        "{%0,%1,%2,%3}, {%4,%5,%6,%7}, {%8,%9}, {%0,%1,%2,%3};\n"
        : "+f"(c[0]), "+f"(c[1]), "+f"(c[2]), "+f"(c[3])
        : "r"(a0), "r"(a1), "r"(a2), "r"(a3), "r"(b0), "r"(b1));
}
__device__ __forceinline__ void cp_async16(uint32_t dst_smem, const void* src) {
    asm volatile("cp.async.cg.shared.global [%0], [%1], 16;\n"
                 :: "r"(dst_smem), "l"(src));
}

// ---- fused prep: x2 -> fp16 K tiles, x4 -> fp16 V^T tiles (256 threads) ----
__global__ void prep_kv_kernel(const float* __restrict__ x2,
                               const float* __restrict__ x4) {
    const int tile = blockIdx.x, b = blockIdx.y;
    const int tid = threadIdx.x;   // 0..255
    __shared__ float raw[TN * 68];

    // K: 64 rows x 16 chunks = 1024 chunks / 256 threads = 4 each
    const float* ksrc = x2 + ((size_t)b * S_ + (size_t)tile * TN) * D_;
    uint32_t* kdst = gK16[b][tile];
    #pragma unroll
    for (int j = 0; j < 4; ++j) {
        int idx = tid + 256 * j;
        int row = idx >> 4, c4 = idx & 15;
        float4 v = *reinterpret_cast<const float4*>(ksrc + row * D_ + 4 * c4);
        kdst[row * 32 + 2 * c4]     = pack_h2(v.x, v.y);
        kdst[row * 32 + 2 * c4 + 1] = pack_h2(v.z, v.w);
    }

    // V: stage raw, then transpose+swizzle+pack
    const float* vsrc = x4 + ((size_t)b * S_ + (size_t)tile * TN) * D_;
    #pragma unroll
    for (int j = 0; j < 4; ++j) {
        int idx = tid + 256 * j;
        int row = idx >> 4, c4 = idx & 15;
        float4 v = *reinterpret_cast<const float4*>(vsrc + row * D_ + 4 * c4);
        *reinterpret_cast<float4*>(raw + row * 68 + 4 * c4) = v;
    }
    __syncthreads();
    uint32_t* vdst = gVT16[b][tile];
    #pragma unroll
    for (int j = 0; j < 8; ++j) {
        int idx = tid + 256 * j;
        int d = idx >> 5, w = idx & 31;
        int f = ((d >> 4) & 3) << 3;
        int tp = w ^ f;
        vdst[d * 32 + w] = pack_h2(raw[(2 * tp) * 68 + d], raw[(2 * tp + 1) * 68 + d]);
    }
}

__global__ void __launch_bounds__(NTHREADS, 2)
attn_bias_kernel(const float* __restrict__ x1,
                 const float* __restrict__ x3,
                 float* __restrict__ out) {
    const int mt = blockIdx.x;   // 0..31 (64-row tiles)
    const int hp = blockIdx.y;   // 0..3  (head pair)
    const int b  = blockIdx.z;   // 0..1

    const int tid  = threadIdx.x;
    const int warp = tid >> 5;
    const int lane = tid & 31;
    const int r = lane >> 2;
    const int q = lane & 3;

    extern __shared__ uint32_t smem[];
    const uint32_t sb = (uint32_t)__cvta_generic_to_shared(smem);
    uint32_t* sQ = smem + OQ;
    const float* sPBf = reinterpret_cast<const float*>(smem + OPB);

    // ---- stage Q tile (64 rows) once: fp16, pre-scaled by 0.125*log2e ----
    const float qs = 0.125f * LOG2E;
    const int srowK = tid >> 4;          // 0..7
    const int sc4   = tid & 15;          // 0..15
    const float* qbase = x1 + ((size_t)b * S_ + (size_t)mt * TM) * D_;
    #pragma unroll
    for (int j = 0; j < 8; ++j) {
        int row = srowK + 8 * j;
        float4 v = *reinterpret_cast<const float4*>(qbase + row * D_ + 4 * sc4);
        uint2 o;
        o.x = pack_h2(v.x * qs, v.y * qs);
        o.y = pack_h2(v.z * qs, v.w * qs);
        *reinterpret_cast<uint2*>(sQ + row * PQW + 2 * sc4) = o;
    }

    float accO[HPC][8][4];
    #pragma unroll
    for (int hh = 0; hh < HPC; ++hh)
        #pragma unroll
        for (int n = 0; n < 8; ++n)
            #pragma unroll
            for (int j = 0; j < 4; ++j) accO[hh][n][j] = 0.0f;
    float accS[HPC][4];
    #pragma unroll
    for (int hh = 0; hh < HPC; ++hh)
        #pragma unroll
        for (int j = 0; j < 4; ++j) accS[hh][j] = 0.0f;

    const int R0 = warp * 16;            // this warp's 16 rows

    // ---- staging geometry ----
    const uint32_t kv_dst_off = 4u * (uint32_t)((tid >> 3) * 36 + (tid & 7) * 4);
    const uint32_t kv_dst_step = 4u * (uint32_t)(16 * 36);
    const uint32_t* gk_src0 = gK16[b][0] + tid * 4;
    const uint32_t* gv_src0 = gVT16[b][0] + tid * 4;
    // bias: warp-local rows [16w, 16w+16) for both heads
    const int brow = warp * 16 + (lane >> 4);   // +2j, j<8
    const int bc4  = lane & 15;
    const size_t bias_rowoff = (size_t)mt * TM + brow;
    const float* bptr0 = x3 + (((size_t)b * H_ + 2 * hp)     * S_ + bias_rowoff) * S_ + bc4 * 4;
    const float* bptr1 = x3 + (((size_t)b * H_ + 2 * hp + 1) * S_ + bias_rowoff) * S_ + bc4 * 4;
    const uint32_t sPB_b0 = sb + 4u * (uint32_t)(OPB + brow * PPW + 4 * bc4);
    const uint32_t sPB_b1 = sPB_b0 + 4u * (uint32_t)(TM * PPW);

    // ---- prologue: kv(0) group, then bias(0) group ----
    {
        const uint32_t dk = sb + 4u * (uint32_t)OK0 + kv_dst_off;
        const uint32_t dv = sb + 4u * (uint32_t)OV0 + kv_dst_off;
        #pragma unroll
        for (int j = 0; j < 4; ++j) {
            cp_async16(dk + j * kv_dst_step, gk_src0 + j * 512);
            cp_async16(dv + j * kv_dst_step, gv_src0 + j * 512);
        }
        asm volatile("cp.async.commit_group;\n" ::: "memory");
    }
    #pragma unroll
    for (int j = 0; j < 8; ++j) {
        cp_async16(sPB_b0 + (uint32_t)(2 * j * PPW) * 4, bptr0 + (size_t)(2 * j) * S_);
        cp_async16(sPB_b1 + (uint32_t)(2 * j * PPW) * 4, bptr1 + (size_t)(2 * j) * S_);
    }
    asm volatile("cp.async.commit_group;\n" ::: "memory");
    bptr0 += TN; bptr1 += TN;

    for (int it = 0; it < NITER; ++it) {
        // ---- kv(it) complete ----
        asm volatile("cp.async.wait_group 1;\n" ::: "memory");
        __syncthreads();

        // ---- issue kv(it+1) ----
        if (it + 1 < NITER) {
            const uint32_t ok = ((it + 1) & 1) ? (uint32_t)OK1 : (uint32_t)OK0;
            const uint32_t ov = ((it + 1) & 1) ? (uint32_t)OV1 : (uint32_t)OV0;
            const uint32_t dk = sb + 4u * ok + kv_dst_off;
            const uint32_t dv = sb + 4u * ov + kv_dst_off;
            const uint32_t* gk = gk_src0 + (size_t)(it + 1) * (TN * 32);
            const uint32_t* gv = gv_src0 + (size_t)(it + 1) * (TN * 32);
            #pragma unroll
            for (int j = 0; j < 4; ++j) {
                cp_async16(dk + j * kv_dst_step, gk + j * 512);
                cp_async16(dv + j * kv_dst_step, gv + j * 512);
            }
            asm volatile("cp.async.commit_group;\n" ::: "memory");
        }

        const uint32_t* sKf = smem + ((it & 1) ? OK1 : OK0);
        const uint32_t* sVT = smem + ((it & 1) ? OV1 : OV0);

        // ---- QK once per CTA (shared by both heads), pre-biased by EOFF ----
        float c[8][4];
        #pragma unroll
        for (int n = 0; n < 8; ++n)
            #pragma unroll
            for (int j = 0; j < 4; ++j) c[n][j] = EOFF;

        #pragma unroll
        for (int k = 0; k < 4; ++k) {
            const uint32_t* qrow0 = sQ + (R0 + r) * PQW + 8 * k + q;
            const uint32_t* qrow1 = sQ + (R0 + r + 8) * PQW + 8 * k + q;
            uint32_t a0 = qrow0[0];
            uint32_t a1 = qrow1[0];
            uint32_t a2 = qrow0[4];
            uint32_t a3 = qrow1[4];
            #pragma unroll
            for (int n = 0; n < 8; ++n) {
                const uint32_t* krow = sKf + (8 * n + r) * PKW + 8 * k + q;
                mma_f16(c[n], a0, a1, a2, a3, krow[0], krow[4]);
            }
        }

        // ---- bias(it) ready ----
        if (it + 1 < NITER) {
            asm volatile("cp.async.wait_group 1;\n" ::: "memory");
        } else {
            asm volatile("cp.async.wait_group 0;\n" ::: "memory");
        }
        __syncwarp();

        // ---- softmax per head: fp16x2 exp2 of offset log2-logits ----
        uint32_t pk[HPC][8][2];
        #pragma unroll
        for (int hh = 0; hh < HPC; ++hh) {
            const float* bh = sPBf + hh * (TM * PPW);
            #pragma unroll
            for (int n = 0; n < 8; ++n) {
                float2 bb0 = *reinterpret_cast<const float2*>(bh + (R0 + r) * PPW + 8 * n + 2 * q);
                float2 bb1 = *reinterpret_cast<const float2*>(bh + (R0 + r + 8) * PPW + 8 * n + 2 * q);
                float e0 = fmaf(bb0.x, LOG2E, c[n][0]);
                float e1 = fmaf(bb0.y, LOG2E, c[n][1]);
                float e2 = fmaf(bb1.x, LOG2E, c[n][2]);
                float e3 = fmaf(bb1.y, LOG2E, c[n][3]);
                pk[hh][n][0] = ex2h2(pack_h2(e0, e1));
                pk[hh][n][1] = ex2h2(pack_h2(e2, e3));
            }
        }

        // ---- issue bias(it+1) ----
        if (it + 1 < NITER) {
            #pragma unroll
            for (int j = 0; j < 8; ++j) {
                cp_async16(sPB_b0 + (uint32_t)(2 * j * PPW) * 4, bptr0 + (size_t)(2 * j) * S_);
                cp_async16(sPB_b1 + (uint32_t)(2 * j * PPW) * 4, bptr1 + (size_t)(2 * j) * S_);
            }
            asm volatile("cp.async.commit_group;\n" ::: "memory");
            bptr0 += TN; bptr1 += TN;
        }

        // ---- row sums (ones-MMA) + PV, V fragments shared across heads ----
        #pragma unroll
        for (int k = 0; k < 4; ++k) {
            mma_f16(accS[0], pk[0][2*k][0], pk[0][2*k][1],
                             pk[0][2*k+1][0], pk[0][2*k+1][1], ONES_H2, ONES_H2);
            mma_f16(accS[1], pk[1][2*k][0], pk[1][2*k][1],
                             pk[1][2*k+1][0], pk[1][2*k+1][1], ONES_H2, ONES_H2);
        }
        #pragma unroll
        for (int n = 0; n < 8; ++n) {
            const int d = 8 * n + r;
            const uint32_t f = (uint32_t)(((d >> 4) & 3) << 3);
            const uint32_t* vrow = sVT + d * PVW;
            #pragma unroll
            for (int k = 0; k < 4; ++k) {
                uint32_t b0 = vrow[(uint32_t)(8 * k + q) ^ f];
                uint32_t b1 = vrow[(uint32_t)(8 * k + q + 4) ^ f];
                mma_f16(accO[0][n], pk[0][2*k][0], pk[0][2*k][1],
                                    pk[0][2*k+1][0], pk[0][2*k+1][1], b0, b1);
                mma_f16(accO[1][n], pk[1][2*k][0], pk[1][2*k][1],
                                    pk[1][2*k+1][0], pk[1][2*k+1][1], b0, b1);
            }
        }
    }

    // ---- finalize both heads ----
    #pragma unroll
    for (int hh = 0; hh < HPC; ++hh) {
        float inv0 = 1.0f / accS[hh][0];
        float inv1 = 1.0f / accS[hh][2];
        float* obase = out + (((size_t)b * H_ + 2 * hp + hh) * S_ + (size_t)mt * TM) * D_;
        #pragma unroll
        for (int n = 0; n < 8; ++n) {
            float2 v0 = make_float2(accO[hh][n][0] * inv0, accO[hh][n][1] * inv0);
            float2 v1 = make_float2(accO[hh][n][2] * inv1, accO[hh][n][3] * inv1);
            *reinterpret_cast<float2*>(obase + (size_t)(R0 + r) * D_ + 8 * n + 2 * q) = v0;
            *reinterpret_cast<float2*>(obase + (size_t)(R0 + r + 8) * D_ + 8 * n + 2 * q) = v1;
        }
    }
}

extern "C" void kernel_launch(void* const* d_in, const int* in_sizes, int n_in,
                              void* d_out, int out_size) {
    (void)in_sizes; (void)n_in; (void)out_size;
    const float* x1 = (const float*)d_in[0];
    const float* x2 = (const float*)d_in[1];
    const float* x3 = (const float*)d_in[2];
    const float* x4 = (const float*)d_in[3];
    float* out = (float*)d_out;

    dim3 pgrid(NTILE, B_);
    prep_kv_kernel<<<pgrid, 256>>>(x2, x4);

    cudaFuncSetAttribute(attn_bias_kernel,
                         cudaFuncAttributeMaxDynamicSharedMemorySize, SMEM_BYTES);

    dim3 grid(S_ / TM, H_ / HPC, B_);   // 32 x 4 x 2 = 256 CTAs
    attn_bias_kernel<<<grid, NTHREADS, SMEM_BYTES>>>(x1, x3, out);
}